// round 1
// baseline (speedup 1.0000x reference)
#include <cuda_runtime.h>
#include <cuda_bf16.h>
#include <mma.h>
#include <cstdint>

using namespace nvcuda;

// ---------------------------------------------------------------------------
// Problem dims
// ---------------------------------------------------------------------------
// B=4, L=4096, C=1024, M=128, P=4, S=64, H=8, hd=128
// NSEG = B*L/S = 256 segments; tokens TOKS = 16384; context T = 132 (pad 136)

static const int TOKS = 16384;     // total tokens
static const int C    = 1024;
static const int MDIM = 128;

// scratch layout (floats)
#define TOKC (16384ull*1024ull)
__device__ float d_scratch[7*16777216 + 2*2097152 + 2*1048576 + 4096 + 4096 + 1024 + 1024];

// ---------------------------------------------------------------------------
// tf32 WMMA GEMM:  C[M,N] = A[M,K] @ op(B)
//   BTN=true : op(B)[k,n] = B[n*K + k]   (B = W[N,K], nn.Linear style)
//   BTN=false: op(B)[k,n] = B[k*N + n]   (plain row-major [K,N])
// Requires M%128==0, N%128==0, K%32==0.
// ---------------------------------------------------------------------------
template<bool BTN>
__global__ __launch_bounds__(256)
void gemm_kernel(const float* __restrict__ A, const float* __restrict__ B,
                 float* __restrict__ Cout, int M, int N, int K)
{
    __shared__ __align__(16) float As[128*36];   // [m][k], ld 36
    __shared__ __align__(16) float Bs[32*132];   // [k][n], ld 132

    const int tid  = threadIdx.x;
    const int warp = tid >> 5;
    const int wm   = warp & 3;   // 4 row warps
    const int wn   = warp >> 2;  // 2 col warps
    const int m0   = blockIdx.y * 128;
    const int n0   = blockIdx.x * 128;

    wmma::fragment<wmma::accumulator,16,16,8,float> cf[2][4];
    #pragma unroll
    for (int i = 0; i < 2; i++)
        #pragma unroll
        for (int j = 0; j < 4; j++)
            wmma::fill_fragment(cf[i][j], 0.0f);

    for (int k0 = 0; k0 < K; k0 += 32) {
        // load A tile: 128x32 = 1024 float4
        #pragma unroll
        for (int i = 0; i < 4; i++) {
            int idx = tid + i*256;
            int r = idx >> 3, c4 = (idx & 7) << 2;
            *reinterpret_cast<float4*>(&As[r*36 + c4]) =
                *reinterpret_cast<const float4*>(&A[(size_t)(m0 + r)*K + k0 + c4]);
        }
        if (BTN) {
            #pragma unroll
            for (int i = 0; i < 4; i++) {
                int idx = tid + i*256;
                int n = idx >> 3, c4 = (idx & 7) << 2;
                float4 v = *reinterpret_cast<const float4*>(&B[(size_t)(n0 + n)*K + k0 + c4]);
                Bs[(c4+0)*132 + n] = v.x;
                Bs[(c4+1)*132 + n] = v.y;
                Bs[(c4+2)*132 + n] = v.z;
                Bs[(c4+3)*132 + n] = v.w;
            }
        } else {
            #pragma unroll
            for (int i = 0; i < 4; i++) {
                int idx = tid + i*256;
                int kk = idx >> 5, c4 = (idx & 31) << 2;
                *reinterpret_cast<float4*>(&Bs[kk*132 + c4]) =
                    *reinterpret_cast<const float4*>(&B[(size_t)(k0 + kk)*N + n0 + c4]);
            }
        }
        __syncthreads();

        #pragma unroll
        for (int kk = 0; kk < 32; kk += 8) {
            wmma::fragment<wmma::matrix_a,16,16,8,wmma::precision::tf32,wmma::row_major> af[2];
            wmma::fragment<wmma::matrix_b,16,16,8,wmma::precision::tf32,wmma::row_major> bf[4];
            #pragma unroll
            for (int i = 0; i < 2; i++) {
                wmma::load_matrix_sync(af[i], &As[(wm*32 + i*16)*36 + kk], 36);
                #pragma unroll
                for (int t = 0; t < af[i].num_elements; t++)
                    af[i].x[t] = wmma::__float_to_tf32(af[i].x[t]);
            }
            #pragma unroll
            for (int j = 0; j < 4; j++) {
                wmma::load_matrix_sync(bf[j], &Bs[kk*132 + wn*64 + j*16], 132);
                #pragma unroll
                for (int t = 0; t < bf[j].num_elements; t++)
                    bf[j].x[t] = wmma::__float_to_tf32(bf[j].x[t]);
            }
            #pragma unroll
            for (int i = 0; i < 2; i++)
                #pragma unroll
                for (int j = 0; j < 4; j++)
                    wmma::mma_sync(cf[i][j], af[i], bf[j], cf[i][j]);
        }
        __syncthreads();
    }

    #pragma unroll
    for (int i = 0; i < 2; i++)
        #pragma unroll
        for (int j = 0; j < 4; j++)
            wmma::store_matrix_sync(&Cout[(size_t)(m0 + wm*32 + i*16)*N + n0 + wn*64 + j*16],
                                    cf[i][j], N, wmma::mem_row_major);
}

// ---------------------------------------------------------------------------
// memory-net LN over M=128: out = LN(maybe_silu(pre + bias)) * g + b [+ mstate]
// one block (128 threads) per row
// ---------------------------------------------------------------------------
__global__ __launch_bounds__(128)
void ln_mem_kernel(const float* __restrict__ pre, const float* __restrict__ bias,
                   const float* __restrict__ g, const float* __restrict__ b,
                   const float* __restrict__ mstate, float* __restrict__ out, int do_silu)
{
    int r = blockIdx.x, t = threadIdx.x;
    float v = pre[(size_t)r*128 + t] + bias[t];
    if (do_silu) v = v / (1.0f + expf(-v));

    float s = v, q = v*v;
    #pragma unroll
    for (int o = 16; o; o >>= 1) {
        s += __shfl_xor_sync(0xffffffffu, s, o);
        q += __shfl_xor_sync(0xffffffffu, q, o);
    }
    __shared__ float red[8];
    if ((t & 31) == 0) { red[t>>5] = s; red[4 + (t>>5)] = q; }
    __syncthreads();
    float S = red[0]+red[1]+red[2]+red[3];
    float Q = red[4]+red[5]+red[6]+red[7];
    float mu  = S * (1.0f/128.0f);
    float var = Q * (1.0f/128.0f) - mu*mu;
    float o = g[t]*(v - mu)*rsqrtf(var + 1e-5f) + b[t];
    if (mstate) o += mstate[t];
    out[(size_t)r*128 + t] = o;
}

// ---------------------------------------------------------------------------
// bias + LN over C=1024: a += bo (written back), ln_out = LN(a)*g + b
// one block (256 threads, 4 elems each) per row
// ---------------------------------------------------------------------------
__global__ __launch_bounds__(256)
void biasln_c_kernel(float* __restrict__ a, const float* __restrict__ bo,
                     const float* __restrict__ g, const float* __restrict__ b,
                     float* __restrict__ lo)
{
    size_t base = (size_t)blockIdx.x * 1024;
    int t = threadIdx.x;
    float4 v  = *reinterpret_cast<float4*>(a + base + t*4);
    float4 bb = *reinterpret_cast<const float4*>(bo + t*4);
    v.x += bb.x; v.y += bb.y; v.z += bb.z; v.w += bb.w;
    *reinterpret_cast<float4*>(a + base + t*4) = v;

    float s = v.x + v.y + v.z + v.w;
    float q = v.x*v.x + v.y*v.y + v.z*v.z + v.w*v.w;
    #pragma unroll
    for (int o = 16; o; o >>= 1) {
        s += __shfl_xor_sync(0xffffffffu, s, o);
        q += __shfl_xor_sync(0xffffffffu, q, o);
    }
    __shared__ float red[16];
    if ((t & 31) == 0) { red[t>>5] = s; red[8 + (t>>5)] = q; }
    __syncthreads();
    float S = 0.f, Q = 0.f;
    #pragma unroll
    for (int i = 0; i < 8; i++) { S += red[i]; Q += red[8+i]; }
    float mu  = S * (1.0f/1024.0f);
    float var = Q * (1.0f/1024.0f) - mu*mu;
    float rs  = rsqrtf(var + 1e-5f);

    float4 gg = *reinterpret_cast<const float4*>(g + t*4);
    float4 b2 = *reinterpret_cast<const float4*>(b + t*4);
    float4 o;
    o.x = gg.x*(v.x - mu)*rs + b2.x;
    o.y = gg.y*(v.y - mu)*rs + b2.y;
    o.z = gg.z*(v.z - mu)*rs + b2.z;
    o.w = gg.w*(v.w - mu)*rs + b2.w;
    *reinterpret_cast<float4*>(lo + base + t*4) = o;
}

// ---------------------------------------------------------------------------
// effective retrieved-path biases: bkr = mha_bk + WkK@mem_out_b (likewise bvr)
// ---------------------------------------------------------------------------
__global__ __launch_bounds__(256)
void fuse_bias_kernel(const float* __restrict__ WkK, const float* __restrict__ WvV,
                      const float* __restrict__ mob,
                      const float* __restrict__ bk, const float* __restrict__ bv,
                      float* __restrict__ bkr, float* __restrict__ bvr)
{
    int i = blockIdx.x & 1023;
    bool isv = blockIdx.x >= 1024;
    const float* W = isv ? WvV : WkK;
    float s = 0.f;
    for (int k = threadIdx.x; k < 1024; k += 256) s += W[(size_t)i*1024 + k] * mob[k];
    #pragma unroll
    for (int o = 16; o; o >>= 1) s += __shfl_xor_sync(0xffffffffu, s, o);
    __shared__ float red[8];
    if ((threadIdx.x & 31) == 0) red[threadIdx.x >> 5] = s;
    __syncthreads();
    if (threadIdx.x == 0) {
        float S = 0.f;
        #pragma unroll
        for (int w = 0; w < 8; w++) S += red[w];
        (isv ? bvr : bkr)[i] = S + (isv ? bv : bk)[i];
    }
}

// persistent-memory k/v rows (bias baked in): kp[p,i] = pm[p]·WkK[i] + bk[i]
__global__ __launch_bounds__(256)
void pm_proj_kernel(const float* __restrict__ pm,
                    const float* __restrict__ WkK, const float* __restrict__ WvV,
                    const float* __restrict__ bk, const float* __restrict__ bv,
                    float* __restrict__ kp, float* __restrict__ vp)
{
    int id  = blockIdx.x;             // 8192 = 2*4*1024
    bool isv = id >= 4096;
    int p = (id & 4095) >> 10;
    int i = id & 1023;
    const float* W = isv ? WvV : WkK;
    float s = 0.f;
    for (int k = threadIdx.x; k < 1024; k += 256) s += pm[p*1024 + k] * W[(size_t)i*1024 + k];
    #pragma unroll
    for (int o = 16; o; o >>= 1) s += __shfl_xor_sync(0xffffffffu, s, o);
    __shared__ float red[8];
    if ((threadIdx.x & 31) == 0) red[threadIdx.x >> 5] = s;
    __syncthreads();
    if (threadIdx.x == 0) {
        float S = 0.f;
        #pragma unroll
        for (int w = 0; w < 8; w++) S += red[w];
        (isv ? vp : kp)[p*1024 + i] = S + (isv ? bv : bk)[i];
    }
}

// ---------------------------------------------------------------------------
// fused attention: one block per (segment, head); S=64, T=132 (pad 136), hd=128
// context k/v rows: [0,64)=retrieved(+bkr), [64,68)=pm (bias baked), [68,132)=x(+bk)
// smem: q[64][128] + k[136][132] + v[136][132] + p[64][136] = 211200 B
// ---------------------------------------------------------------------------
#define ATTN_SMEM 211200
__global__ __launch_bounds__(256)
void attn_kernel(const float* __restrict__ q,
                 const float* __restrict__ kx, const float* __restrict__ kr, const float* __restrict__ kp,
                 const float* __restrict__ vx, const float* __restrict__ vr, const float* __restrict__ vp,
                 const float* __restrict__ bq, const float* __restrict__ bk, const float* __restrict__ bkr,
                 const float* __restrict__ bv, const float* __restrict__ bvr,
                 float* __restrict__ out)
{
    extern __shared__ __align__(16) float sm[];
    float* qs = sm;                       // 64*128
    float* ks = qs + 64*128;              // 136*132
    float* vs = ks + 136*132;             // 136*132
    float* ps = vs + 136*132;             // 64*136

    const int seg = blockIdx.x;
    const int h   = blockIdx.y;
    const int tid = threadIdx.x;
    const int c0  = h * 128;
    const float scale = 0.08838834764831845f;  // 1/sqrt(128)

    // q (+bq, *scale)
    for (int i = tid; i < 64*32; i += 256) {
        int r = i >> 5, c4 = (i & 31) << 2;
        float4 v = *reinterpret_cast<const float4*>(q + (size_t)(seg*64 + r)*1024 + c0 + c4);
        float4 b = *reinterpret_cast<const float4*>(bq + c0 + c4);
        float* d = qs + r*128 + c4;
        d[0] = (v.x + b.x)*scale; d[1] = (v.y + b.y)*scale;
        d[2] = (v.z + b.z)*scale; d[3] = (v.w + b.w)*scale;
    }
    // k rows
    for (int i = tid; i < 136*32; i += 256) {
        int r = i >> 5, c4 = (i & 31) << 2;
        float4 v = {0,0,0,0}, b = {0,0,0,0};
        if (r < 64) {
            v = *reinterpret_cast<const float4*>(kr + (size_t)(seg*64 + r)*1024 + c0 + c4);
            b = *reinterpret_cast<const float4*>(bkr + c0 + c4);
        } else if (r < 68) {
            v = *reinterpret_cast<const float4*>(kp + (size_t)(r - 64)*1024 + c0 + c4);
        } else if (r < 132) {
            v = *reinterpret_cast<const float4*>(kx + (size_t)(seg*64 + r - 68)*1024 + c0 + c4);
            b = *reinterpret_cast<const float4*>(bk + c0 + c4);
        }
        float* d = ks + r*132 + c4;
        d[0] = v.x + b.x; d[1] = v.y + b.y; d[2] = v.z + b.z; d[3] = v.w + b.w;
    }
    // v rows
    for (int i = tid; i < 136*32; i += 256) {
        int r = i >> 5, c4 = (i & 31) << 2;
        float4 v = {0,0,0,0}, b = {0,0,0,0};
        if (r < 64) {
            v = *reinterpret_cast<const float4*>(vr + (size_t)(seg*64 + r)*1024 + c0 + c4);
            b = *reinterpret_cast<const float4*>(bvr + c0 + c4);
        } else if (r < 68) {
            v = *reinterpret_cast<const float4*>(vp + (size_t)(r - 64)*1024 + c0 + c4);
        } else if (r < 132) {
            v = *reinterpret_cast<const float4*>(vx + (size_t)(seg*64 + r - 68)*1024 + c0 + c4);
            b = *reinterpret_cast<const float4*>(bv + c0 + c4);
        }
        float* d = vs + r*132 + c4;
        d[0] = v.x + b.x; d[1] = v.y + b.y; d[2] = v.z + b.z; d[3] = v.w + b.w;
    }
    __syncthreads();

    // scores: 4x4 register tiles over [64][136]
    for (int t0 = tid; t0 < 16*34; t0 += 256) {
        int r0  = (t0 / 34) * 4;
        int cc0 = (t0 % 34) * 4;
        float acc[4][4] = {};
        for (int k = 0; k < 128; k += 4) {
            float4 a0 = *reinterpret_cast<const float4*>(qs + (r0+0)*128 + k);
            float4 a1 = *reinterpret_cast<const float4*>(qs + (r0+1)*128 + k);
            float4 a2 = *reinterpret_cast<const float4*>(qs + (r0+2)*128 + k);
            float4 a3 = *reinterpret_cast<const float4*>(qs + (r0+3)*128 + k);
            float4 b0 = *reinterpret_cast<const float4*>(ks + (cc0+0)*132 + k);
            float4 b1 = *reinterpret_cast<const float4*>(ks + (cc0+1)*132 + k);
            float4 b2 = *reinterpret_cast<const float4*>(ks + (cc0+2)*132 + k);
            float4 b3 = *reinterpret_cast<const float4*>(ks + (cc0+3)*132 + k);
            #define DOT4(A,B) (A.x*B.x + A.y*B.y + A.z*B.z + A.w*B.w)
            acc[0][0] += DOT4(a0,b0); acc[0][1] += DOT4(a0,b1); acc[0][2] += DOT4(a0,b2); acc[0][3] += DOT4(a0,b3);
            acc[1][0] += DOT4(a1,b0); acc[1][1] += DOT4(a1,b1); acc[1][2] += DOT4(a1,b2); acc[1][3] += DOT4(a1,b3);
            acc[2][0] += DOT4(a2,b0); acc[2][1] += DOT4(a2,b1); acc[2][2] += DOT4(a2,b2); acc[2][3] += DOT4(a2,b3);
            acc[3][0] += DOT4(a3,b0); acc[3][1] += DOT4(a3,b1); acc[3][2] += DOT4(a3,b2); acc[3][3] += DOT4(a3,b3);
            #undef DOT4
        }
        #pragma unroll
        for (int i = 0; i < 4; i++)
            #pragma unroll
            for (int j = 0; j < 4; j++)
                ps[(r0+i)*136 + cc0 + j] = (cc0 + j < 132) ? acc[i][j] : -1e30f;
    }
    __syncthreads();

    // softmax per row (64 rows, thread t < 64 owns row t)
    if (tid < 64) {
        float* row = ps + tid*136;
        float m = -1e30f;
        for (int c = 0; c < 136; c++) m = fmaxf(m, row[c]);
        float s = 0.f;
        for (int c = 0; c < 136; c++) { float e = expf(row[c] - m); row[c] = e; s += e; }
        float inv = 1.0f / s;
        for (int c = 0; c < 136; c++) row[c] *= inv;
    }
    __syncthreads();

    // p @ v: 4x4 tiles over [64][128]
    for (int t0 = tid; t0 < 16*32; t0 += 256) {
        int r0 = (t0 >> 5) * 4;
        int d0 = (t0 & 31) * 4;
        float acc[4][4] = {};
        for (int c = 0; c < 136; c++) {
            float4 vv = *reinterpret_cast<const float4*>(vs + c*132 + d0);
            float p0 = ps[(r0+0)*136 + c];
            float p1 = ps[(r0+1)*136 + c];
            float p2 = ps[(r0+2)*136 + c];
            float p3 = ps[(r0+3)*136 + c];
            acc[0][0] += p0*vv.x; acc[0][1] += p0*vv.y; acc[0][2] += p0*vv.z; acc[0][3] += p0*vv.w;
            acc[1][0] += p1*vv.x; acc[1][1] += p1*vv.y; acc[1][2] += p1*vv.z; acc[1][3] += p1*vv.w;
            acc[2][0] += p2*vv.x; acc[2][1] += p2*vv.y; acc[2][2] += p2*vv.z; acc[2][3] += p2*vv.w;
            acc[3][0] += p3*vv.x; acc[3][1] += p3*vv.y; acc[3][2] += p3*vv.z; acc[3][3] += p3*vv.w;
        }
        #pragma unroll
        for (int i = 0; i < 4; i++)
            #pragma unroll
            for (int j = 0; j < 4; j++)
                out[(size_t)(seg*64 + r0 + i)*1024 + c0 + d0 + j] = acc[i][j];
    }
}

// gate blend: u = sigmoid(gpre + gate_b) * attn_biased + x
__global__ __launch_bounds__(256)
void e2_kernel(const float* __restrict__ gpre, const float* __restrict__ gb,
               const float* __restrict__ attnb, const float* __restrict__ x,
               float* __restrict__ u)
{
    for (size_t idx = (size_t)blockIdx.x*blockDim.x + threadIdx.x;
         idx < 16777216ull; idx += (size_t)gridDim.x*blockDim.x) {
        int c = (int)(idx & 1023);
        float g = 1.0f / (1.0f + expf(-(gpre[idx] + gb[c])));
        u[idx] = g * attnb[idx] + x[idx];
    }
}

__global__ __launch_bounds__(256)
void add_bias_kernel(float* __restrict__ out, const float* __restrict__ ob)
{
    for (size_t idx = (size_t)blockIdx.x*blockDim.x + threadIdx.x;
         idx < 16777216ull; idx += (size_t)gridDim.x*blockDim.x)
        out[idx] += ob[idx & 1023];
}

// ---------------------------------------------------------------------------
extern "C" void kernel_launch(void* const* d_in, const int* in_sizes, int n_in,
                              void* d_out, int out_size)
{
    const float* x      = (const float*)d_in[0];
    const float* pm     = (const float*)d_in[1];
    const float* Wq     = (const float*)d_in[2];
    const float* Wk     = (const float*)d_in[3];
    const float* Wv     = (const float*)d_in[4];
    const float* mem_W1 = (const float*)d_in[5];
    const float* mem_b1 = (const float*)d_in[6];
    const float* ln1_g  = (const float*)d_in[7];
    const float* ln1_b  = (const float*)d_in[8];
    const float* mem_W2 = (const float*)d_in[9];
    const float* mem_b2 = (const float*)d_in[10];
    const float* ln2_g  = (const float*)d_in[11];
    const float* ln2_b  = (const float*)d_in[12];
    const float* mem_oW = (const float*)d_in[13];
    const float* mem_ob = (const float*)d_in[14];
    const float* mstate = (const float*)d_in[15];
    const float* mha_Wq = (const float*)d_in[16];
    const float* mha_bq = (const float*)d_in[17];
    const float* mha_Wk = (const float*)d_in[18];
    const float* mha_bk = (const float*)d_in[19];
    const float* mha_Wv = (const float*)d_in[20];
    const float* mha_bv = (const float*)d_in[21];
    const float* mha_Wo = (const float*)d_in[22];
    const float* mha_bo = (const float*)d_in[23];
    const float* gn_g   = (const float*)d_in[24];
    const float* gn_b   = (const float*)d_in[25];
    const float* gate_W = (const float*)d_in[26];
    const float* gate_b = (const float*)d_in[27];
    const float* out_W  = (const float*)d_in[28];
    const float* out_b  = (const float*)d_in[29];
    float* out = (float*)d_out;

    void* sp; cudaGetSymbolAddress(&sp, d_scratch);
    float* S0 = (float*)sp;
    float* qseg = S0;
    float* ret  = S0 + 1*TOKC;
    float* kx   = S0 + 2*TOKC;
    float* kr   = S0 + 3*TOKC;
    float* vx   = S0 + 4*TOKC;
    float* vr   = S0 + 5*TOKC;
    float* qb   = S0 + 6*TOKC;
    float* m1   = S0 + 7*TOKC;
    float* m2   = m1  + (size_t)16384*128;
    float* WkK  = m2  + (size_t)16384*128;
    float* WvV  = WkK + 1024*1024;
    float* kp   = WvV + 1024*1024;
    float* vp   = kp  + 4096;
    float* bkr  = vp  + 4096;
    float* bvr  = bkr + 1024;

    dim3 blk(256);
    dim3 gBig(8, 128);   // 16384x1024
    dim3 gMem(1, 128);   // 16384x128
    dim3 gW(8, 8);       // 1024x1024

    // 1) q_seg = x @ Wq^T
    gemm_kernel<true><<<gBig, blk>>>(x, Wq, qseg, 16384, 1024, 1024);
    // 2) memory net
    gemm_kernel<true><<<gMem, blk>>>(qseg, mem_W1, m1, 16384, 128, 1024);
    ln_mem_kernel<<<16384, 128>>>(m1, mem_b1, ln1_g, ln1_b, nullptr, m2, 1);
    gemm_kernel<true><<<gMem, blk>>>(m2, mem_W2, m1, 16384, 128, 128);
    ln_mem_kernel<<<16384, 128>>>(m1, mem_b2, ln2_g, ln2_b, mstate, m2, 0);
    gemm_kernel<true><<<gBig, blk>>>(m2, mem_oW, ret, 16384, 1024, 128);   // retrieved (no bias)
    // 3) fused projection weights WkK = mha_Wk@Wk, WvV = mha_Wv@Wv
    gemm_kernel<false><<<gW, blk>>>(mha_Wk, Wk, WkK, 1024, 1024, 1024);
    gemm_kernel<false><<<gW, blk>>>(mha_Wv, Wv, WvV, 1024, 1024, 1024);
    fuse_bias_kernel<<<2048, 256>>>(WkK, WvV, mem_ob, mha_bk, mha_bv, bkr, bvr);
    pm_proj_kernel<<<8192, 256>>>(pm, WkK, WvV, mha_bk, mha_bv, kp, vp);
    // 4) k/v for x-rows and retrieved-rows of the context
    gemm_kernel<true><<<gBig, blk>>>(x,   WkK, kx, 16384, 1024, 1024);
    gemm_kernel<true><<<gBig, blk>>>(ret, WkK, kr, 16384, 1024, 1024);
    gemm_kernel<true><<<gBig, blk>>>(x,   WvV, vx, 16384, 1024, 1024);
    gemm_kernel<true><<<gBig, blk>>>(ret, WvV, vr, 16384, 1024, 1024);
    // 5) q
    gemm_kernel<true><<<gBig, blk>>>(qseg, mha_Wq, qb, 16384, 1024, 1024);
    // 6) attention -> reuse qseg as attn output
    cudaFuncSetAttribute(attn_kernel, cudaFuncAttributeMaxDynamicSharedMemorySize, ATTN_SMEM);
    attn_kernel<<<dim3(256, 8), 256, ATTN_SMEM>>>(qb, kx, kr, kp, vx, vr, vp,
                                                  mha_bq, mha_bk, bkr, mha_bv, bvr, qseg);
    // 7) out proj of attention -> ret (attnp), then bias+LN -> kx (attn_ln)
    gemm_kernel<true><<<gBig, blk>>>(qseg, mha_Wo, ret, 16384, 1024, 1024);
    biasln_c_kernel<<<16384, 256>>>(ret, mha_bo, gn_g, gn_b, kx);
    // 8) gate
    gemm_kernel<true><<<gBig, blk>>>(kx, gate_W, kr, 16384, 1024, 1024);
    e2_kernel<<<8192, 256>>>(kr, gate_b, ret, x, vx);
    // 9) output projection
    gemm_kernel<true><<<gBig, blk>>>(vx, out_W, out, 16384, 1024, 1024);
    add_bias_kernel<<<8192, 256>>>(out, out_b);
}

// round 2
// speedup vs baseline: 2.2681x; 2.2681x over previous
#include <cuda_runtime.h>
#include <cuda_bf16.h>
#include <mma.h>
#include <cstdint>

using namespace nvcuda;

// B=4, L=4096, C=1024, M=128, P=4, S=64, H=8, hd=128
// NSEG=256, TOKS=16384, context T=132 (scores padded to 144, pv k=136)

// ---------------------------------------------------------------------------
// scratch (floats)
// ---------------------------------------------------------------------------
#define TOKC   16777216ull            // 16384*1024
#define TOK2C  33554432ull            // 16384*2048
__device__ float d_scratch[2*33554432ull + 4*16777216ull + 3*2097152ull
                           + 1048576 + 2097152 + 262144 + 131072 + 16384];

__device__ __forceinline__ void cp16(uint32_t s, const float* g) {
    asm volatile("cp.async.cg.shared.global [%0], [%1], 16;\n" :: "r"(s), "l"(g) : "memory");
}

// ---------------------------------------------------------------------------
// Pipelined tf32 GEMM:  C[M,N] = A[M,K] @ W^T,  W = [N,K] (nn.Linear weight)
// 128x128 tile, Kstep 32, cp.async double buffer. M%128==0, N%128==0, K%32==0.
// ---------------------------------------------------------------------------
__global__ __launch_bounds__(256)
void gemm_t_kernel(const float* __restrict__ A, const float* __restrict__ W,
                   float* __restrict__ Cout, int M, int N, int K)
{
    extern __shared__ __align__(16) float sm[];
    float* As = sm;               // [2][128*36]
    float* Bs = sm + 2*128*36;    // [2][128*36]  (stored [n][k])

    const int tid  = threadIdx.x;
    const int warp = tid >> 5;
    const int wm   = warp & 3;
    const int wn   = warp >> 2;
    const int m0   = blockIdx.y * 128;
    const int n0   = blockIdx.x * 128;
    const int nk   = K >> 5;

    wmma::fragment<wmma::accumulator,16,16,8,float> cf[2][4];
    #pragma unroll
    for (int i = 0; i < 2; i++)
        #pragma unroll
        for (int j = 0; j < 4; j++)
            wmma::fill_fragment(cf[i][j], 0.0f);

    // prologue: tile 0 -> buf 0
    {
        const float* Ag = A + (size_t)m0*K;
        const float* Wg = W + (size_t)n0*K;
        uint32_t sA = (uint32_t)__cvta_generic_to_shared(As);
        uint32_t sB = (uint32_t)__cvta_generic_to_shared(Bs);
        #pragma unroll
        for (int i = 0; i < 4; i++) {
            int ch = tid + i*256;
            int r = ch >> 3, c = (ch & 7) << 2;
            cp16(sA + (uint32_t)(r*36 + c)*4u, Ag + (size_t)r*K + c);
            cp16(sB + (uint32_t)(r*36 + c)*4u, Wg + (size_t)r*K + c);
        }
        asm volatile("cp.async.commit_group;\n" ::: "memory");
    }

    int buf = 0;
    for (int it = 0; it < nk; it++) {
        asm volatile("cp.async.wait_group 0;\n" ::: "memory");
        __syncthreads();

        if (it + 1 < nk) {
            const float* Ag = A + (size_t)m0*K + (it+1)*32;
            const float* Wg = W + (size_t)n0*K + (it+1)*32;
            int nb = buf ^ 1;
            uint32_t sA = (uint32_t)__cvta_generic_to_shared(As + nb*4608);
            uint32_t sB = (uint32_t)__cvta_generic_to_shared(Bs + nb*4608);
            #pragma unroll
            for (int i = 0; i < 4; i++) {
                int ch = tid + i*256;
                int r = ch >> 3, c = (ch & 7) << 2;
                cp16(sA + (uint32_t)(r*36 + c)*4u, Ag + (size_t)r*K + c);
                cp16(sB + (uint32_t)(r*36 + c)*4u, Wg + (size_t)r*K + c);
            }
            asm volatile("cp.async.commit_group;\n" ::: "memory");
        }

        const float* Ab = As + buf*4608;
        const float* Bb = Bs + buf*4608;
        #pragma unroll
        for (int kk = 0; kk < 32; kk += 8) {
            wmma::fragment<wmma::matrix_a,16,16,8,wmma::precision::tf32,wmma::row_major> af[2];
            wmma::fragment<wmma::matrix_b,16,16,8,wmma::precision::tf32,wmma::col_major> bf[4];
            #pragma unroll
            for (int i = 0; i < 2; i++) {
                wmma::load_matrix_sync(af[i], Ab + (wm*32 + i*16)*36 + kk, 36);
                #pragma unroll
                for (int t = 0; t < af[i].num_elements; t++)
                    af[i].x[t] = wmma::__float_to_tf32(af[i].x[t]);
            }
            #pragma unroll
            for (int j = 0; j < 4; j++) {
                wmma::load_matrix_sync(bf[j], Bb + (wn*64 + j*16)*36 + kk, 36);
                #pragma unroll
                for (int t = 0; t < bf[j].num_elements; t++)
                    bf[j].x[t] = wmma::__float_to_tf32(bf[j].x[t]);
            }
            #pragma unroll
            for (int i = 0; i < 2; i++)
                #pragma unroll
                for (int j = 0; j < 4; j++)
                    wmma::mma_sync(cf[i][j], af[i], bf[j], cf[i][j]);
        }
        buf ^= 1;
    }

    #pragma unroll
    for (int i = 0; i < 2; i++)
        #pragma unroll
        for (int j = 0; j < 4; j++)
            wmma::store_matrix_sync(&Cout[(size_t)(m0 + wm*32 + i*16)*N + n0 + wn*64 + j*16],
                                    cf[i][j], N, wmma::mem_row_major);
}

// ---------------------------------------------------------------------------
// simple tf32 GEMM (weight prep):  C[M,N] = A[M,K] @ B[K,N]  (B row-major)
// ---------------------------------------------------------------------------
__global__ __launch_bounds__(256)
void gemm_nt_kernel(const float* __restrict__ A, const float* __restrict__ B,
                    float* __restrict__ Cout, int M, int N, int K)
{
    __shared__ __align__(16) float As[128*36];
    __shared__ __align__(16) float Bs[32*132];

    const int tid  = threadIdx.x;
    const int warp = tid >> 5;
    const int wm   = warp & 3;
    const int wn   = warp >> 2;
    const int m0   = blockIdx.y * 128;
    const int n0   = blockIdx.x * 128;

    wmma::fragment<wmma::accumulator,16,16,8,float> cf[2][4];
    #pragma unroll
    for (int i = 0; i < 2; i++)
        #pragma unroll
        for (int j = 0; j < 4; j++)
            wmma::fill_fragment(cf[i][j], 0.0f);

    for (int k0 = 0; k0 < K; k0 += 32) {
        #pragma unroll
        for (int i = 0; i < 4; i++) {
            int idx = tid + i*256;
            int r = idx >> 3, c4 = (idx & 7) << 2;
            *reinterpret_cast<float4*>(&As[r*36 + c4]) =
                *reinterpret_cast<const float4*>(&A[(size_t)(m0 + r)*K + k0 + c4]);
        }
        #pragma unroll
        for (int i = 0; i < 4; i++) {
            int idx = tid + i*256;
            int kk = idx >> 5, c4 = (idx & 31) << 2;
            *reinterpret_cast<float4*>(&Bs[kk*132 + c4]) =
                *reinterpret_cast<const float4*>(&B[(size_t)(k0 + kk)*N + n0 + c4]);
        }
        __syncthreads();

        #pragma unroll
        for (int kk = 0; kk < 32; kk += 8) {
            wmma::fragment<wmma::matrix_a,16,16,8,wmma::precision::tf32,wmma::row_major> af[2];
            wmma::fragment<wmma::matrix_b,16,16,8,wmma::precision::tf32,wmma::row_major> bf[4];
            #pragma unroll
            for (int i = 0; i < 2; i++) {
                wmma::load_matrix_sync(af[i], &As[(wm*32 + i*16)*36 + kk], 36);
                #pragma unroll
                for (int t = 0; t < af[i].num_elements; t++)
                    af[i].x[t] = wmma::__float_to_tf32(af[i].x[t]);
            }
            #pragma unroll
            for (int j = 0; j < 4; j++) {
                wmma::load_matrix_sync(bf[j], &Bs[kk*132 + wn*64 + j*16], 132);
                #pragma unroll
                for (int t = 0; t < bf[j].num_elements; t++)
                    bf[j].x[t] = wmma::__float_to_tf32(bf[j].x[t]);
            }
            #pragma unroll
            for (int i = 0; i < 2; i++)
                #pragma unroll
                for (int j = 0; j < 4; j++)
                    wmma::mma_sync(cf[i][j], af[i], bf[j], cf[i][j]);
        }
        __syncthreads();
    }

    #pragma unroll
    for (int i = 0; i < 2; i++)
        #pragma unroll
        for (int j = 0; j < 4; j++)
            wmma::store_matrix_sync(&Cout[(size_t)(m0 + wm*32 + i*16)*N + n0 + wn*64 + j*16],
                                    cf[i][j], N, wmma::mem_row_major);
}

// ---------------------------------------------------------------------------
// memory-net LN over M=128 (silu optional, +mstate optional)
// ---------------------------------------------------------------------------
__global__ __launch_bounds__(128)
void ln_mem_kernel(const float* __restrict__ pre, const float* __restrict__ bias,
                   const float* __restrict__ g, const float* __restrict__ b,
                   const float* __restrict__ mstate, float* __restrict__ out, int do_silu)
{
    int r = blockIdx.x, t = threadIdx.x;
    float v = pre[(size_t)r*128 + t] + bias[t];
    if (do_silu) v = v / (1.0f + __expf(-v));

    float s = v, q = v*v;
    #pragma unroll
    for (int o = 16; o; o >>= 1) {
        s += __shfl_xor_sync(0xffffffffu, s, o);
        q += __shfl_xor_sync(0xffffffffu, q, o);
    }
    __shared__ float red[8];
    if ((t & 31) == 0) { red[t>>5] = s; red[4 + (t>>5)] = q; }
    __syncthreads();
    float S = red[0]+red[1]+red[2]+red[3];
    float Q = red[4]+red[5]+red[6]+red[7];
    float mu  = S * (1.0f/128.0f);
    float var = Q * (1.0f/128.0f) - mu*mu;
    float o = g[t]*(v - mu)*rsqrtf(var + 1e-5f) + b[t];
    if (mstate) o += mstate[t];
    out[(size_t)r*128 + t] = o;
}

// bias + LN over C=1024: a += bo (in place), lo = LN(a)*g + b
__global__ __launch_bounds__(256)
void biasln_c_kernel(float* __restrict__ a, const float* __restrict__ bo,
                     const float* __restrict__ g, const float* __restrict__ b,
                     float* __restrict__ lo)
{
    size_t base = (size_t)blockIdx.x * 1024;
    int t = threadIdx.x;
    float4 v  = *reinterpret_cast<float4*>(a + base + t*4);
    float4 bb = *reinterpret_cast<const float4*>(bo + t*4);
    v.x += bb.x; v.y += bb.y; v.z += bb.z; v.w += bb.w;
    *reinterpret_cast<float4*>(a + base + t*4) = v;

    float s = v.x + v.y + v.z + v.w;
    float q = v.x*v.x + v.y*v.y + v.z*v.z + v.w*v.w;
    #pragma unroll
    for (int o = 16; o; o >>= 1) {
        s += __shfl_xor_sync(0xffffffffu, s, o);
        q += __shfl_xor_sync(0xffffffffu, q, o);
    }
    __shared__ float red[16];
    if ((t & 31) == 0) { red[t>>5] = s; red[8 + (t>>5)] = q; }
    __syncthreads();
    float S = 0.f, Q = 0.f;
    #pragma unroll
    for (int i = 0; i < 8; i++) { S += red[i]; Q += red[8+i]; }
    float mu  = S * (1.0f/1024.0f);
    float var = Q * (1.0f/1024.0f) - mu*mu;
    float rs  = rsqrtf(var + 1e-5f);

    float4 gg = *reinterpret_cast<const float4*>(g + t*4);
    float4 b2 = *reinterpret_cast<const float4*>(b + t*4);
    float4 o;
    o.x = gg.x*(v.x - mu)*rs + b2.x;
    o.y = gg.y*(v.y - mu)*rs + b2.y;
    o.z = gg.z*(v.z - mu)*rs + b2.z;
    o.w = gg.w*(v.w - mu)*rs + b2.w;
    *reinterpret_cast<float4*>(lo + base + t*4) = o;
}

// bkr = bk + WkK@mem_ob (likewise bvr)
__global__ __launch_bounds__(256)
void fuse_bias_kernel(const float* __restrict__ WkK, const float* __restrict__ WvV,
                      const float* __restrict__ mob,
                      const float* __restrict__ bk, const float* __restrict__ bv,
                      float* __restrict__ bkr, float* __restrict__ bvr)
{
    int i = blockIdx.x & 1023;
    bool isv = blockIdx.x >= 1024;
    const float* W = isv ? WvV : WkK;
    float s = 0.f;
    for (int k = threadIdx.x; k < 1024; k += 256) s += W[(size_t)i*1024 + k] * mob[k];
    #pragma unroll
    for (int o = 16; o; o >>= 1) s += __shfl_xor_sync(0xffffffffu, s, o);
    __shared__ float red[8];
    if ((threadIdx.x & 31) == 0) red[threadIdx.x >> 5] = s;
    __syncthreads();
    if (threadIdx.x == 0) {
        float S = 0.f;
        #pragma unroll
        for (int w = 0; w < 8; w++) S += red[w];
        (isv ? bvr : bkr)[i] = S + (isv ? bv : bk)[i];
    }
}

// persistent-memory k/v rows (bias baked in)
__global__ __launch_bounds__(256)
void pm_proj_kernel(const float* __restrict__ pm,
                    const float* __restrict__ WkK, const float* __restrict__ WvV,
                    const float* __restrict__ bk, const float* __restrict__ bv,
                    float* __restrict__ kp, float* __restrict__ vp)
{
    int id  = blockIdx.x;
    bool isv = id >= 4096;
    int p = (id & 4095) >> 10;
    int i = id & 1023;
    const float* W = isv ? WvV : WkK;
    float s = 0.f;
    for (int k = threadIdx.x; k < 1024; k += 256) s += pm[p*1024 + k] * W[(size_t)i*1024 + k];
    #pragma unroll
    for (int o = 16; o; o >>= 1) s += __shfl_xor_sync(0xffffffffu, s, o);
    __shared__ float red[8];
    if ((threadIdx.x & 31) == 0) red[threadIdx.x >> 5] = s;
    __syncthreads();
    if (threadIdx.x == 0) {
        float S = 0.f;
        #pragma unroll
        for (int w = 0; w < 8; w++) S += red[w];
        (isv ? vp : kp)[p*1024 + i] = S + (isv ? bv : bk)[i];
    }
}

// ---------------------------------------------------------------------------
// tensor-core attention: one block per (segment, head); 8 warps
// k/v rows: [0,64)=retrieved(+bkr/bvr), [64,68)=pm, [68,132)=x(+bk/bv)
// qs[64][132], ks[144][132] (rows>=132 zero), vs[136][132], ps[64][148]
// ---------------------------------------------------------------------------
#define ATTN_SMEM ((64*132 + 144*132 + 136*132 + 64*148)*4)
__global__ __launch_bounds__(256)
void attn_kernel(const float* __restrict__ q,
                 const float* __restrict__ kvx,   // [16384][2048] (k | v)
                 const float* __restrict__ kvr,   // [16384][2048] (k | v)
                 const float* __restrict__ kp, const float* __restrict__ vp,
                 const float* __restrict__ bq, const float* __restrict__ bk,
                 const float* __restrict__ bkr,
                 const float* __restrict__ bv, const float* __restrict__ bvr,
                 float* __restrict__ out)
{
    extern __shared__ __align__(16) float sm[];
    float* qs = sm;                 // 64*132
    float* ks = qs + 64*132;        // 144*132
    float* vs = ks + 144*132;       // 136*132
    float* ps = vs + 136*132;       // 64*148

    const int seg  = blockIdx.x;
    const int h    = blockIdx.y;
    const int tid  = threadIdx.x;
    const int warp = tid >> 5;
    const int lane = tid & 31;
    const int c0   = h * 128;
    const float scale = 0.08838834764831845f;   // 1/sqrt(128)

    // ---- load q (+bq)*scale
    for (int i = tid; i < 64*32; i += 256) {
        int r = i >> 5, c4 = (i & 31) << 2;
        float4 v = *reinterpret_cast<const float4*>(q + (size_t)(seg*64 + r)*1024 + c0 + c4);
        float4 b = *reinterpret_cast<const float4*>(bq + c0 + c4);
        float* d = qs + r*132 + c4;
        d[0] = (v.x + b.x)*scale; d[1] = (v.y + b.y)*scale;
        d[2] = (v.z + b.z)*scale; d[3] = (v.w + b.w)*scale;
    }
    // ---- load k rows (144, zero pad >=132)
    for (int i = tid; i < 144*32; i += 256) {
        int r = i >> 5, c4 = (i & 31) << 2;
        float4 v = {0,0,0,0}, b = {0,0,0,0};
        if (r < 64) {
            v = *reinterpret_cast<const float4*>(kvr + (size_t)(seg*64 + r)*2048 + c0 + c4);
            b = *reinterpret_cast<const float4*>(bkr + c0 + c4);
        } else if (r < 68) {
            v = *reinterpret_cast<const float4*>(kp + (size_t)(r - 64)*1024 + c0 + c4);
        } else if (r < 132) {
            v = *reinterpret_cast<const float4*>(kvx + (size_t)(seg*64 + r - 68)*2048 + c0 + c4);
            b = *reinterpret_cast<const float4*>(bk + c0 + c4);
        }
        float* d = ks + r*132 + c4;
        d[0] = v.x + b.x; d[1] = v.y + b.y; d[2] = v.z + b.z; d[3] = v.w + b.w;
    }
    // ---- load v rows (136, zero pad >=132)
    for (int i = tid; i < 136*32; i += 256) {
        int r = i >> 5, c4 = (i & 31) << 2;
        float4 v = {0,0,0,0}, b = {0,0,0,0};
        if (r < 64) {
            v = *reinterpret_cast<const float4*>(kvr + (size_t)(seg*64 + r)*2048 + 1024 + c0 + c4);
            b = *reinterpret_cast<const float4*>(bvr + c0 + c4);
        } else if (r < 68) {
            v = *reinterpret_cast<const float4*>(vp + (size_t)(r - 64)*1024 + c0 + c4);
        } else if (r < 132) {
            v = *reinterpret_cast<const float4*>(kvx + (size_t)(seg*64 + r - 68)*2048 + 1024 + c0 + c4);
            b = *reinterpret_cast<const float4*>(bv + c0 + c4);
        }
        float* d = vs + r*132 + c4;
        d[0] = v.x + b.x; d[1] = v.y + b.y; d[2] = v.z + b.z; d[3] = v.w + b.w;
    }
    __syncthreads();

    // ---- scores = qs @ ks^T   (64 x 144, wmma tf32)
    for (int t = warp; t < 36; t += 8) {
        int ms = (t / 9) * 16;
        int ns = (t % 9) * 16;
        wmma::fragment<wmma::accumulator,16,16,8,float> acc;
        wmma::fill_fragment(acc, 0.0f);
        #pragma unroll
        for (int kk = 0; kk < 128; kk += 8) {
            wmma::fragment<wmma::matrix_a,16,16,8,wmma::precision::tf32,wmma::row_major> af;
            wmma::fragment<wmma::matrix_b,16,16,8,wmma::precision::tf32,wmma::col_major> bf;
            wmma::load_matrix_sync(af, qs + ms*132 + kk, 132);
            wmma::load_matrix_sync(bf, ks + ns*132 + kk, 132);
            #pragma unroll
            for (int e = 0; e < af.num_elements; e++) af.x[e] = wmma::__float_to_tf32(af.x[e]);
            #pragma unroll
            for (int e = 0; e < bf.num_elements; e++) bf.x[e] = wmma::__float_to_tf32(bf.x[e]);
            wmma::mma_sync(acc, af, bf, acc);
        }
        wmma::store_matrix_sync(ps + ms*148 + ns, acc, 148, wmma::mem_row_major);
    }
    __syncthreads();

    // ---- softmax: warp w handles rows 8w..8w+7 (132 valid cols)
    for (int r = warp*8; r < warp*8 + 8; r++) {
        float* row = ps + r*148;
        float m = -1e30f;
        for (int c = lane; c < 132; c += 32) m = fmaxf(m, row[c]);
        #pragma unroll
        for (int o = 16; o; o >>= 1) m = fmaxf(m, __shfl_xor_sync(0xffffffffu, m, o));
        float s = 0.f;
        for (int c = lane; c < 132; c += 32) { float e = __expf(row[c] - m); row[c] = e; s += e; }
        #pragma unroll
        for (int o = 16; o; o >>= 1) s += __shfl_xor_sync(0xffffffffu, s, o);
        float inv = 1.0f / s;
        for (int c = lane; c < 132; c += 32) row[c] *= inv;
        if (lane < 4) row[132 + lane] = 0.0f;   // zero pad for pv (k up to 136)
    }
    __syncthreads();

    // ---- out = ps @ vs   (64 x 128, k = 136)
    for (int t = warp; t < 32; t += 8) {
        int ms = (t >> 3) * 16;
        int ds = (t & 7) * 16;
        wmma::fragment<wmma::accumulator,16,16,8,float> acc;
        wmma::fill_fragment(acc, 0.0f);
        #pragma unroll
        for (int kk = 0; kk < 136; kk += 8) {
            wmma::fragment<wmma::matrix_a,16,16,8,wmma::precision::tf32,wmma::row_major> af;
            wmma::fragment<wmma::matrix_b,16,16,8,wmma::precision::tf32,wmma::row_major> bf;
            wmma::load_matrix_sync(af, ps + ms*148 + kk, 148);
            wmma::load_matrix_sync(bf, vs + kk*132 + ds, 132);
            #pragma unroll
            for (int e = 0; e < af.num_elements; e++) af.x[e] = wmma::__float_to_tf32(af.x[e]);
            #pragma unroll
            for (int e = 0; e < bf.num_elements; e++) bf.x[e] = wmma::__float_to_tf32(bf.x[e]);
            wmma::mma_sync(acc, af, bf, acc);
        }
        wmma::store_matrix_sync(&out[(size_t)(seg*64 + ms)*1024 + c0 + ds], acc, 1024,
                                wmma::mem_row_major);
    }
}

// gate blend: u = sigmoid(gpre + gate_b) * attn_biased + x
__global__ __launch_bounds__(256)
void e2_kernel(const float* __restrict__ gpre, const float* __restrict__ gb,
               const float* __restrict__ attnb, const float* __restrict__ x,
               float* __restrict__ u)
{
    for (size_t idx = (size_t)blockIdx.x*blockDim.x + threadIdx.x;
         idx < 16777216ull; idx += (size_t)gridDim.x*blockDim.x) {
        int c = (int)(idx & 1023);
        float g = 1.0f / (1.0f + __expf(-(gpre[idx] + gb[c])));
        u[idx] = g * attnb[idx] + x[idx];
    }
}

__global__ __launch_bounds__(256)
void add_bias_kernel(float* __restrict__ out, const float* __restrict__ ob)
{
    for (size_t idx = (size_t)blockIdx.x*blockDim.x + threadIdx.x;
         idx < 16777216ull; idx += (size_t)gridDim.x*blockDim.x)
        out[idx] += ob[idx & 1023];
}

// ---------------------------------------------------------------------------
extern "C" void kernel_launch(void* const* d_in, const int* in_sizes, int n_in,
                              void* d_out, int out_size)
{
    const float* x      = (const float*)d_in[0];
    const float* pm     = (const float*)d_in[1];
    const float* Wq     = (const float*)d_in[2];
    const float* Wk     = (const float*)d_in[3];
    const float* Wv     = (const float*)d_in[4];
    const float* mem_W1 = (const float*)d_in[5];
    const float* mem_b1 = (const float*)d_in[6];
    const float* ln1_g  = (const float*)d_in[7];
    const float* ln1_b  = (const float*)d_in[8];
    const float* mem_W2 = (const float*)d_in[9];
    const float* mem_b2 = (const float*)d_in[10];
    const float* ln2_g  = (const float*)d_in[11];
    const float* ln2_b  = (const float*)d_in[12];
    const float* mem_oW = (const float*)d_in[13];
    const float* mem_ob = (const float*)d_in[14];
    const float* mstate = (const float*)d_in[15];
    const float* mha_Wq = (const float*)d_in[16];
    const float* mha_bq = (const float*)d_in[17];
    const float* mha_Wk = (const float*)d_in[18];
    const float* mha_bk = (const float*)d_in[19];
    const float* mha_Wv = (const float*)d_in[20];
    const float* mha_bv = (const float*)d_in[21];
    const float* mha_Wo = (const float*)d_in[22];
    const float* mha_bo = (const float*)d_in[23];
    const float* gn_g   = (const float*)d_in[24];
    const float* gn_b   = (const float*)d_in[25];
    const float* gate_W = (const float*)d_in[26];
    const float* gate_b = (const float*)d_in[27];
    const float* out_W  = (const float*)d_in[28];
    const float* out_b  = (const float*)d_in[29];
    float* out = (float*)d_out;

    void* sp; cudaGetSymbolAddress(&sp, d_scratch);
    float* S0   = (float*)sp;
    float* kvx  = S0;                          // [16384][2048]
    float* kvr  = kvx + TOK2C;                 // [16384][2048]
    float* A2   = kvr + TOK2C;                 // qb, later gpre
    float* A3   = A2  + TOKC;                  // attn out
    float* A4   = A3  + TOKC;                  // attnp (biased)
    float* A5   = A4  + TOKC;                  // attn_ln
    float* m1   = A5  + TOKC;                  // [16384][128]
    float* m2a  = m1  + (size_t)16384*128;
    float* m2   = m2a + (size_t)16384*128;
    float* Wqq  = m2  + (size_t)16384*128;     // [1024][1024]
    float* Wkv  = Wqq + 1048576;               // [2048][1024] = WkK | WvV
    float* Wkrv = Wkv + 2097152;               // [2048][128]  = WkrM | WvrM
    float* W1q  = Wkrv + 262144;               // [128][1024]
    float* kp   = W1q + 131072;
    float* vp   = kp + 4096;
    float* bkr  = vp + 4096;
    float* bvr  = bkr + 1024;
    float* WkK  = Wkv;
    float* WvV  = Wkv + 1048576;

    static int inited = 0;
    cudaFuncSetAttribute(gemm_t_kernel, cudaFuncAttributeMaxDynamicSharedMemorySize, 73728);
    cudaFuncSetAttribute(attn_kernel,  cudaFuncAttributeMaxDynamicSharedMemorySize, ATTN_SMEM);
    (void)inited;

    dim3 blk(256);
    const int GSM = 73728;

    // ---- weight prep (fold Wq / mem_oW into downstream projections)
    gemm_nt_kernel<<<dim3(8,8), blk>>>(mha_Wq, Wq, Wqq, 1024, 1024, 1024);
    gemm_nt_kernel<<<dim3(8,8), blk>>>(mha_Wk, Wk, WkK, 1024, 1024, 1024);
    gemm_nt_kernel<<<dim3(8,8), blk>>>(mha_Wv, Wv, WvV, 1024, 1024, 1024);
    gemm_nt_kernel<<<dim3(8,1), blk>>>(mem_W1, Wq, W1q, 128, 1024, 1024);
    gemm_nt_kernel<<<dim3(1,8), blk>>>(WkK, mem_oW, Wkrv,          1024, 128, 1024);
    gemm_nt_kernel<<<dim3(1,8), blk>>>(WvV, mem_oW, Wkrv + 131072, 1024, 128, 1024);
    fuse_bias_kernel<<<2048, 256>>>(WkK, WvV, mem_ob, mha_bk, mha_bv, bkr, bvr);
    pm_proj_kernel<<<8192, 256>>>(pm, WkK, WvV, mha_bk, mha_bv, kp, vp);

    // ---- memory net (on x directly via W1q)
    gemm_t_kernel<<<dim3(1,128), blk, GSM>>>(x, W1q, m1, 16384, 128, 1024);
    ln_mem_kernel<<<16384, 128>>>(m1, mem_b1, ln1_g, ln1_b, nullptr, m2a, 1);
    gemm_t_kernel<<<dim3(1,128), blk, GSM>>>(m2a, mem_W2, m1, 16384, 128, 128);
    ln_mem_kernel<<<16384, 128>>>(m1, mem_b2, ln2_g, ln2_b, mstate, m2, 0);

    // ---- projections
    gemm_t_kernel<<<dim3(8,128),  blk, GSM>>>(x,  Wqq,  A2,  16384, 1024, 1024);  // q
    gemm_t_kernel<<<dim3(16,128), blk, GSM>>>(x,  Wkv,  kvx, 16384, 2048, 1024);  // kx|vx
    gemm_t_kernel<<<dim3(16,128), blk, GSM>>>(m2, Wkrv, kvr, 16384, 2048, 128);   // kr|vr

    // ---- attention
    attn_kernel<<<dim3(256, 8), 256, ATTN_SMEM>>>(A2, kvx, kvr, kp, vp,
                                                  mha_bq, mha_bk, bkr, mha_bv, bvr, A3);

    // ---- output path
    gemm_t_kernel<<<dim3(8,128), blk, GSM>>>(A3, mha_Wo, A4, 16384, 1024, 1024);
    biasln_c_kernel<<<16384, 256>>>(A4, mha_bo, gn_g, gn_b, A5);
    gemm_t_kernel<<<dim3(8,128), blk, GSM>>>(A5, gate_W, A2, 16384, 1024, 1024);
    e2_kernel<<<8192, 256>>>(A2, gate_b, A4, x, kvx);
    gemm_t_kernel<<<dim3(8,128), blk, GSM>>>(kvx, out_W, out, 16384, 1024, 1024);
    add_bias_kernel<<<8192, 256>>>(out, out_b);
}

// round 4
// speedup vs baseline: 2.3492x; 1.0358x over previous
#include <cuda_runtime.h>
#include <cuda_bf16.h>
#include <mma.h>
#include <cstdint>

using namespace nvcuda;

// B=4, L=4096, C=1024, M=128, P=4, S=64, H=8, hd=128
// NSEG=256, TOKS=16384, context T=132

#define TOKC 16777216ull
__device__ float d_scratch[144100000ull];

__device__ __forceinline__ void cp16(uint32_t s, const float* g) {
    asm volatile("cp.async.cg.shared.global [%0], [%1], 16;\n" :: "r"(s), "l"(g) : "memory");
}

// ---------------------------------------------------------------------------
// 4-stage pipelined tf32 GEMM.
//   BTN=true : C[M,N] = A[M,K] @ W^T, W=[N,K] row-major (nn.Linear weight)
//   BTN=false: C[M,N] = A[M,K] @ B,   B=[K,N] row-major
// 128x128 tile, Kstep 32. M%128==0, N%128==0, K%32==0.
// smem: 4 stages x (As 4608 + Bs 4608) floats = 147456 B
// ---------------------------------------------------------------------------
#define STG 4
#define STRIDE_S 4608

template<bool BTN>
__device__ __forceinline__ void load_tile(const float* __restrict__ A,
                                          const float* __restrict__ B,
                                          int N, int K, int m0, int n0, int it,
                                          float* As, float* Bs, int tid)
{
    const float* Ag = A + (size_t)m0*K + it*32;
    uint32_t sA = (uint32_t)__cvta_generic_to_shared(As);
    uint32_t sB = (uint32_t)__cvta_generic_to_shared(Bs);
    #pragma unroll
    for (int i = 0; i < 4; i++) {
        int ch = tid + i*256;
        int r = ch >> 3, c = (ch & 7) << 2;
        cp16(sA + (uint32_t)(r*36 + c)*4u, Ag + (size_t)r*K + c);
    }
    if (BTN) {
        const float* Wg = B + (size_t)n0*K + it*32;
        #pragma unroll
        for (int i = 0; i < 4; i++) {
            int ch = tid + i*256;
            int r = ch >> 3, c = (ch & 7) << 2;
            cp16(sB + (uint32_t)(r*36 + c)*4u, Wg + (size_t)r*K + c);
        }
    } else {
        const float* Bg = B + (size_t)(it*32)*N + n0;
        #pragma unroll
        for (int i = 0; i < 4; i++) {
            int ch = tid + i*256;
            int kk = ch >> 5, c = (ch & 31) << 2;
            cp16(sB + (uint32_t)(kk*132 + c)*4u, Bg + (size_t)kk*N + c);
        }
    }
}

template<bool BTN>
__global__ __launch_bounds__(256)
void gemm_p_kernel(const float* __restrict__ A, const float* __restrict__ B,
                   float* __restrict__ Cout, int M, int N, int K)
{
    extern __shared__ __align__(16) float sm[];
    float* As = sm;                       // [STG][4608]
    float* Bs = sm + STG*STRIDE_S;        // [STG][4608]

    const int tid  = threadIdx.x;
    const int warp = tid >> 5;
    const int wm   = warp & 3;
    const int wn   = warp >> 2;
    const int m0   = blockIdx.y * 128;
    const int n0   = blockIdx.x * 128;
    const int nk   = K >> 5;

    wmma::fragment<wmma::accumulator,16,16,8,float> cf[2][4];
    #pragma unroll
    for (int i = 0; i < 2; i++)
        #pragma unroll
        for (int j = 0; j < 4; j++)
            wmma::fill_fragment(cf[i][j], 0.0f);

    // prologue: stages 0..2
    #pragma unroll
    for (int s = 0; s < STG-1; s++) {
        if (s < nk)
            load_tile<BTN>(A, B, N, K, m0, n0, s, As + s*STRIDE_S, Bs + s*STRIDE_S, tid);
        asm volatile("cp.async.commit_group;\n" ::: "memory");
    }

    for (int it = 0; it < nk; it++) {
        if (it + STG-1 < nk) {
            int slot = (it + STG-1) & (STG-1);
            load_tile<BTN>(A, B, N, K, m0, n0, it + STG-1,
                           As + slot*STRIDE_S, Bs + slot*STRIDE_S, tid);
        }
        asm volatile("cp.async.commit_group;\n" ::: "memory");
        asm volatile("cp.async.wait_group %0;\n" :: "n"(STG-1) : "memory");
        __syncthreads();

        const float* Ab = As + (it & (STG-1))*STRIDE_S;
        const float* Bb = Bs + (it & (STG-1))*STRIDE_S;
        #pragma unroll
        for (int kk = 0; kk < 32; kk += 8) {
            wmma::fragment<wmma::matrix_a,16,16,8,wmma::precision::tf32,wmma::row_major> af[2];
            #pragma unroll
            for (int i = 0; i < 2; i++) {
                wmma::load_matrix_sync(af[i], Ab + (wm*32 + i*16)*36 + kk, 36);
                #pragma unroll
                for (int t = 0; t < af[i].num_elements; t++)
                    af[i].x[t] = wmma::__float_to_tf32(af[i].x[t]);
            }
            if (BTN) {
                wmma::fragment<wmma::matrix_b,16,16,8,wmma::precision::tf32,wmma::col_major> bf[4];
                #pragma unroll
                for (int j = 0; j < 4; j++) {
                    wmma::load_matrix_sync(bf[j], Bb + (wn*64 + j*16)*36 + kk, 36);
                    #pragma unroll
                    for (int t = 0; t < bf[j].num_elements; t++)
                        bf[j].x[t] = wmma::__float_to_tf32(bf[j].x[t]);
                }
                #pragma unroll
                for (int i = 0; i < 2; i++)
                    #pragma unroll
                    for (int j = 0; j < 4; j++)
                        wmma::mma_sync(cf[i][j], af[i], bf[j], cf[i][j]);
            } else {
                wmma::fragment<wmma::matrix_b,16,16,8,wmma::precision::tf32,wmma::row_major> bf[4];
                #pragma unroll
                for (int j = 0; j < 4; j++) {
                    wmma::load_matrix_sync(bf[j], Bb + kk*132 + wn*64 + j*16, 132);
                    #pragma unroll
                    for (int t = 0; t < bf[j].num_elements; t++)
                        bf[j].x[t] = wmma::__float_to_tf32(bf[j].x[t]);
                }
                #pragma unroll
                for (int i = 0; i < 2; i++)
                    #pragma unroll
                    for (int j = 0; j < 4; j++)
                        wmma::mma_sync(cf[i][j], af[i], bf[j], cf[i][j]);
            }
        }
        __syncthreads();
    }

    #pragma unroll
    for (int i = 0; i < 2; i++)
        #pragma unroll
        for (int j = 0; j < 4; j++)
            wmma::store_matrix_sync(&Cout[(size_t)(m0 + wm*32 + i*16)*N + n0 + wn*64 + j*16],
                                    cf[i][j], N, wmma::mem_row_major);
}

#define GSM (2*STG*STRIDE_S*4)

// ---------------------------------------------------------------------------
// memory-net LN over M=128 (silu optional, +mstate optional)
// ---------------------------------------------------------------------------
__global__ __launch_bounds__(128)
void ln_mem_kernel(const float* __restrict__ pre, const float* __restrict__ bias,
                   const float* __restrict__ g, const float* __restrict__ b,
                   const float* __restrict__ mstate, float* __restrict__ out, int do_silu)
{
    int r = blockIdx.x, t = threadIdx.x;
    float v = pre[(size_t)r*128 + t] + bias[t];
    if (do_silu) v = v / (1.0f + __expf(-v));

    float s = v, q = v*v;
    #pragma unroll
    for (int o = 16; o; o >>= 1) {
        s += __shfl_xor_sync(0xffffffffu, s, o);
        q += __shfl_xor_sync(0xffffffffu, q, o);
    }
    __shared__ float red[8];
    if ((t & 31) == 0) { red[t>>5] = s; red[4 + (t>>5)] = q; }
    __syncthreads();
    float S = red[0]+red[1]+red[2]+red[3];
    float Q = red[4]+red[5]+red[6]+red[7];
    float mu  = S * (1.0f/128.0f);
    float var = Q * (1.0f/128.0f) - mu*mu;
    float o = g[t]*(v - mu)*rsqrtf(var + 1e-5f) + b[t];
    if (mstate) o += mstate[t];
    out[(size_t)r*128 + t] = o;
}

// bias + LN over C=1024: a += bo (in place), lo = LN(a)*g + b
__global__ __launch_bounds__(256)
void biasln_c_kernel(float* __restrict__ a, const float* __restrict__ bo,
                     const float* __restrict__ g, const float* __restrict__ b,
                     float* __restrict__ lo)
{
    size_t base = (size_t)blockIdx.x * 1024;
    int t = threadIdx.x;
    float4 v  = *reinterpret_cast<float4*>(a + base + t*4);
    float4 bb = *reinterpret_cast<const float4*>(bo + t*4);
    v.x += bb.x; v.y += bb.y; v.z += bb.z; v.w += bb.w;
    *reinterpret_cast<float4*>(a + base + t*4) = v;

    float s = v.x + v.y + v.z + v.w;
    float q = v.x*v.x + v.y*v.y + v.z*v.z + v.w*v.w;
    #pragma unroll
    for (int o = 16; o; o >>= 1) {
        s += __shfl_xor_sync(0xffffffffu, s, o);
        q += __shfl_xor_sync(0xffffffffu, q, o);
    }
    __shared__ float red[16];
    if ((t & 31) == 0) { red[t>>5] = s; red[8 + (t>>5)] = q; }
    __syncthreads();
    float S = 0.f, Q = 0.f;
    #pragma unroll
    for (int i = 0; i < 8; i++) { S += red[i]; Q += red[8+i]; }
    float mu  = S * (1.0f/1024.0f);
    float var = Q * (1.0f/1024.0f) - mu*mu;
    float rs  = rsqrtf(var + 1e-5f);

    float4 gg = *reinterpret_cast<const float4*>(g + t*4);
    float4 b2 = *reinterpret_cast<const float4*>(b + t*4);
    float4 o;
    o.x = gg.x*(v.x - mu)*rs + b2.x;
    o.y = gg.y*(v.y - mu)*rs + b2.y;
    o.z = gg.z*(v.z - mu)*rs + b2.z;
    o.w = gg.w*(v.w - mu)*rs + b2.w;
    *reinterpret_cast<float4*>(lo + base + t*4) = o;
}

// bkr = bk + WkK@mem_ob (likewise bvr)
__global__ __launch_bounds__(256)
void fuse_bias_kernel(const float* __restrict__ WkK, const float* __restrict__ WvV,
                      const float* __restrict__ mob,
                      const float* __restrict__ bk, const float* __restrict__ bv,
                      float* __restrict__ bkr, float* __restrict__ bvr)
{
    int i = blockIdx.x & 1023;
    bool isv = blockIdx.x >= 1024;
    const float* W = isv ? WvV : WkK;
    float s = 0.f;
    for (int k = threadIdx.x; k < 1024; k += 256) s += W[(size_t)i*1024 + k] * mob[k];
    #pragma unroll
    for (int o = 16; o; o >>= 1) s += __shfl_xor_sync(0xffffffffu, s, o);
    __shared__ float red[8];
    if ((threadIdx.x & 31) == 0) red[threadIdx.x >> 5] = s;
    __syncthreads();
    if (threadIdx.x == 0) {
        float S = 0.f;
        #pragma unroll
        for (int w = 0; w < 8; w++) S += red[w];
        (isv ? bvr : bkr)[i] = S + (isv ? bv : bk)[i];
    }
}

// persistent-memory k/v rows (bias baked in)
__global__ __launch_bounds__(256)
void pm_proj_kernel(const float* __restrict__ pm,
                    const float* __restrict__ WkK, const float* __restrict__ WvV,
                    const float* __restrict__ bk, const float* __restrict__ bv,
                    float* __restrict__ kp, float* __restrict__ vp)
{
    int id  = blockIdx.x;
    bool isv = id >= 4096;
    int p = (id & 4095) >> 10;
    int i = id & 1023;
    const float* W = isv ? WvV : WkK;
    float s = 0.f;
    for (int k = threadIdx.x; k < 1024; k += 256) s += pm[p*1024 + k] * W[(size_t)i*1024 + k];
    #pragma unroll
    for (int o = 16; o; o >>= 1) s += __shfl_xor_sync(0xffffffffu, s, o);
    __shared__ float red[8];
    if ((threadIdx.x & 31) == 0) red[threadIdx.x >> 5] = s;
    __syncthreads();
    if (threadIdx.x == 0) {
        float S = 0.f;
        #pragma unroll
        for (int w = 0; w < 8; w++) S += red[w];
        (isv ? vp : kp)[p*1024 + i] = S + (isv ? bv : bk)[i];
    }
}

// ---------------------------------------------------------------------------
// tensor-core attention: one block per (segment, head); 8 warps
// q/kx/vx come from qkv[16384][3072] (offsets 0 / 1024 / 2048)
// kr/vr from kvr[16384][2048]
// ---------------------------------------------------------------------------
#define ATTN_SMEM ((64*132 + 144*132 + 136*132 + 64*148)*4)
__global__ __launch_bounds__(256)
void attn_kernel(const float* __restrict__ qkv,
                 const float* __restrict__ kvr,
                 const float* __restrict__ kp, const float* __restrict__ vp,
                 const float* __restrict__ bq, const float* __restrict__ bk,
                 const float* __restrict__ bkr,
                 const float* __restrict__ bv, const float* __restrict__ bvr,
                 float* __restrict__ out)
{
    extern __shared__ __align__(16) float sm[];
    float* qs = sm;                 // 64*132
    float* ks = qs + 64*132;        // 144*132
    float* vs = ks + 144*132;       // 136*132
    float* ps = vs + 136*132;       // 64*148

    const int seg  = blockIdx.x;
    const int h    = blockIdx.y;
    const int tid  = threadIdx.x;
    const int warp = tid >> 5;
    const int lane = tid & 31;
    const int c0   = h * 128;
    const float scale = 0.08838834764831845f;   // 1/sqrt(128)

    // q (+bq)*scale
    for (int i = tid; i < 64*32; i += 256) {
        int r = i >> 5, c4 = (i & 31) << 2;
        float4 v = *reinterpret_cast<const float4*>(qkv + (size_t)(seg*64 + r)*3072 + c0 + c4);
        float4 b = *reinterpret_cast<const float4*>(bq + c0 + c4);
        float* d = qs + r*132 + c4;
        d[0] = (v.x + b.x)*scale; d[1] = (v.y + b.y)*scale;
        d[2] = (v.z + b.z)*scale; d[3] = (v.w + b.w)*scale;
    }
    // k rows (144, zero pad >=132)
    for (int i = tid; i < 144*32; i += 256) {
        int r = i >> 5, c4 = (i & 31) << 2;
        float4 v = {0,0,0,0}, b = {0,0,0,0};
        if (r < 64) {
            v = *reinterpret_cast<const float4*>(kvr + (size_t)(seg*64 + r)*2048 + c0 + c4);
            b = *reinterpret_cast<const float4*>(bkr + c0 + c4);
        } else if (r < 68) {
            v = *reinterpret_cast<const float4*>(kp + (size_t)(r - 64)*1024 + c0 + c4);
        } else if (r < 132) {
            v = *reinterpret_cast<const float4*>(qkv + (size_t)(seg*64 + r - 68)*3072 + 1024 + c0 + c4);
            b = *reinterpret_cast<const float4*>(bk + c0 + c4);
        }
        float* d = ks + r*132 + c4;
        d[0] = v.x + b.x; d[1] = v.y + b.y; d[2] = v.z + b.z; d[3] = v.w + b.w;
    }
    // v rows (136, zero pad >=132)
    for (int i = tid; i < 136*32; i += 256) {
        int r = i >> 5, c4 = (i & 31) << 2;
        float4 v = {0,0,0,0}, b = {0,0,0,0};
        if (r < 64) {
            v = *reinterpret_cast<const float4*>(kvr + (size_t)(seg*64 + r)*2048 + 1024 + c0 + c4);
            b = *reinterpret_cast<const float4*>(bvr + c0 + c4);
        } else if (r < 68) {
            v = *reinterpret_cast<const float4*>(vp + (size_t)(r - 64)*1024 + c0 + c4);
        } else if (r < 132) {
            v = *reinterpret_cast<const float4*>(qkv + (size_t)(seg*64 + r - 68)*3072 + 2048 + c0 + c4);
            b = *reinterpret_cast<const float4*>(bv + c0 + c4);
        }
        float* d = vs + r*132 + c4;
        d[0] = v.x + b.x; d[1] = v.y + b.y; d[2] = v.z + b.z; d[3] = v.w + b.w;
    }
    __syncthreads();

    // scores = qs @ ks^T (64 x 144)
    for (int t = warp; t < 36; t += 8) {
        int ms = (t / 9) * 16;
        int ns = (t % 9) * 16;
        wmma::fragment<wmma::accumulator,16,16,8,float> acc;
        wmma::fill_fragment(acc, 0.0f);
        #pragma unroll
        for (int kk = 0; kk < 128; kk += 8) {
            wmma::fragment<wmma::matrix_a,16,16,8,wmma::precision::tf32,wmma::row_major> af;
            wmma::fragment<wmma::matrix_b,16,16,8,wmma::precision::tf32,wmma::col_major> bf;
            wmma::load_matrix_sync(af, qs + ms*132 + kk, 132);
            wmma::load_matrix_sync(bf, ks + ns*132 + kk, 132);
            #pragma unroll
            for (int e = 0; e < af.num_elements; e++) af.x[e] = wmma::__float_to_tf32(af.x[e]);
            #pragma unroll
            for (int e = 0; e < bf.num_elements; e++) bf.x[e] = wmma::__float_to_tf32(bf.x[e]);
            wmma::mma_sync(acc, af, bf, acc);
        }
        wmma::store_matrix_sync(ps + ms*148 + ns, acc, 148, wmma::mem_row_major);
    }
    __syncthreads();

    // softmax: warp w handles rows 8w..8w+7 (132 valid cols)
    for (int r = warp*8; r < warp*8 + 8; r++) {
        float* row = ps + r*148;
        float m = -1e30f;
        for (int c = lane; c < 132; c += 32) m = fmaxf(m, row[c]);
        #pragma unroll
        for (int o = 16; o; o >>= 1) m = fmaxf(m, __shfl_xor_sync(0xffffffffu, m, o));
        float s = 0.f;
        for (int c = lane; c < 132; c += 32) { float e = __expf(row[c] - m); row[c] = e; s += e; }
        #pragma unroll
        for (int o = 16; o; o >>= 1) s += __shfl_xor_sync(0xffffffffu, s, o);
        float inv = 1.0f / s;
        for (int c = lane; c < 132; c += 32) row[c] *= inv;
        if (lane < 4) row[132 + lane] = 0.0f;
    }
    __syncthreads();

    // out = ps @ vs (64 x 128, k=136)
    for (int t = warp; t < 32; t += 8) {
        int ms = (t >> 3) * 16;
        int ds = (t & 7) * 16;
        wmma::fragment<wmma::accumulator,16,16,8,float> acc;
        wmma::fill_fragment(acc, 0.0f);
        #pragma unroll
        for (int kk = 0; kk < 136; kk += 8) {
            wmma::fragment<wmma::matrix_a,16,16,8,wmma::precision::tf32,wmma::row_major> af;
            wmma::fragment<wmma::matrix_b,16,16,8,wmma::precision::tf32,wmma::row_major> bf;
            wmma::load_matrix_sync(af, ps + ms*148 + kk, 148);
            wmma::load_matrix_sync(bf, vs + kk*132 + ds, 132);
            #pragma unroll
            for (int e = 0; e < af.num_elements; e++) af.x[e] = wmma::__float_to_tf32(af.x[e]);
            #pragma unroll
            for (int e = 0; e < bf.num_elements; e++) bf.x[e] = wmma::__float_to_tf32(bf.x[e]);
            wmma::mma_sync(acc, af, bf, acc);
        }
        wmma::store_matrix_sync(&out[(size_t)(seg*64 + ms)*1024 + c0 + ds], acc, 1024,
                                wmma::mem_row_major);
    }
}

// gate blend: u = sigmoid(gpre + gate_b) * attn_biased + x
__global__ __launch_bounds__(256)
void e2_kernel(const float* __restrict__ gpre, const float* __restrict__ gb,
               const float* __restrict__ attnb, const float* __restrict__ x,
               float* __restrict__ u)
{
    for (size_t idx = (size_t)blockIdx.x*blockDim.x + threadIdx.x;
         idx < 16777216ull; idx += (size_t)gridDim.x*blockDim.x) {
        int c = (int)(idx & 1023);
        float g = 1.0f / (1.0f + __expf(-(gpre[idx] + gb[c])));
        u[idx] = g * attnb[idx] + x[idx];
    }
}

__global__ __launch_bounds__(256)
void add_bias_kernel(float* __restrict__ out, const float* __restrict__ ob)
{
    for (size_t idx = (size_t)blockIdx.x*blockDim.x + threadIdx.x;
         idx < 16777216ull; idx += (size_t)gridDim.x*blockDim.x)
        out[idx] += ob[idx & 1023];
}

// ---------------------------------------------------------------------------
extern "C" void kernel_launch(void* const* d_in, const int* in_sizes, int n_in,
                              void* d_out, int out_size)
{
    const float* x      = (const float*)d_in[0];
    const float* pm     = (const float*)d_in[1];
    const float* Wq     = (const float*)d_in[2];
    const float* Wk     = (const float*)d_in[3];
    const float* Wv     = (const float*)d_in[4];
    const float* mem_W1 = (const float*)d_in[5];
    const float* mem_b1 = (const float*)d_in[6];
    const float* ln1_g  = (const float*)d_in[7];
    const float* ln1_b  = (const float*)d_in[8];
    const float* mem_W2 = (const float*)d_in[9];
    const float* mem_b2 = (const float*)d_in[10];
    const float* ln2_g  = (const float*)d_in[11];
    const float* ln2_b  = (const float*)d_in[12];
    const float* mem_oW = (const float*)d_in[13];
    const float* mem_ob = (const float*)d_in[14];
    const float* mstate = (const float*)d_in[15];
    const float* mha_Wq = (const float*)d_in[16];
    const float* mha_bq = (const float*)d_in[17];
    const float* mha_Wk = (const float*)d_in[18];
    const float* mha_bk = (const float*)d_in[19];
    const float* mha_Wv = (const float*)d_in[20];
    const float* mha_bv = (const float*)d_in[21];
    const float* mha_Wo = (const float*)d_in[22];
    const float* mha_bo = (const float*)d_in[23];
    const float* gn_g   = (const float*)d_in[24];
    const float* gn_b   = (const float*)d_in[25];
    const float* gate_W = (const float*)d_in[26];
    const float* gate_b = (const float*)d_in[27];
    const float* out_W  = (const float*)d_in[28];
    const float* out_b  = (const float*)d_in[29];
    float* out = (float*)d_out;

    void* sp; cudaGetSymbolAddress(&sp, d_scratch);
    float* S0   = (float*)sp;
    float* qkv  = S0;                               // [16384][3072]
    float* kvr  = qkv + (size_t)16384*3072;          // [16384][2048]
    float* A3   = kvr + (size_t)16384*2048;          // attn out
    float* A4   = A3  + TOKC;                        // attnp (biased)
    float* A5   = A4  + TOKC;                        // attn_ln / u
    float* m1   = A5  + TOKC;                        // [16384][128]
    float* m2a  = m1  + (size_t)16384*128;
    float* m2   = m2a + (size_t)16384*128;
    float* Wall = m2  + (size_t)16384*128;           // [3072][1024] = Wqq|WkK|WvV
    float* Wkrv = Wall + (size_t)3072*1024;          // [2048][128]
    float* W1q  = Wkrv + 262144;                     // [128][1024]
    float* kp   = W1q + 131072;
    float* vp   = kp + 4096;
    float* bkr  = vp + 4096;
    float* bvr  = bkr + 1024;
    float* Wqq  = Wall;
    float* WkK  = Wall + 1048576;
    float* WvV  = Wall + 2097152;

    cudaFuncSetAttribute(gemm_p_kernel<true>,  cudaFuncAttributeMaxDynamicSharedMemorySize, GSM);
    cudaFuncSetAttribute(gemm_p_kernel<false>, cudaFuncAttributeMaxDynamicSharedMemorySize, GSM);
    cudaFuncSetAttribute(attn_kernel, cudaFuncAttributeMaxDynamicSharedMemorySize, ATTN_SMEM);

    dim3 blk(256);

    // ---- weight prep
    gemm_p_kernel<false><<<dim3(8,8), blk, GSM>>>(mha_Wq, Wq, Wqq, 1024, 1024, 1024);
    gemm_p_kernel<false><<<dim3(8,8), blk, GSM>>>(mha_Wk, Wk, WkK, 1024, 1024, 1024);
    gemm_p_kernel<false><<<dim3(8,8), blk, GSM>>>(mha_Wv, Wv, WvV, 1024, 1024, 1024);
    gemm_p_kernel<false><<<dim3(8,1), blk, GSM>>>(mem_W1, Wq, W1q, 128, 1024, 1024);
    gemm_p_kernel<false><<<dim3(1,8), blk, GSM>>>(WkK, mem_oW, Wkrv,          1024, 128, 1024);
    gemm_p_kernel<false><<<dim3(1,8), blk, GSM>>>(WvV, mem_oW, Wkrv + 131072, 1024, 128, 1024);
    fuse_bias_kernel<<<2048, 256>>>(WkK, WvV, mem_ob, mha_bk, mha_bv, bkr, bvr);
    pm_proj_kernel<<<8192, 256>>>(pm, WkK, WvV, mha_bk, mha_bv, kp, vp);

    // ---- memory net (on x directly via W1q)
    gemm_p_kernel<true><<<dim3(1,128), blk, GSM>>>(x, W1q, m1, 16384, 128, 1024);
    ln_mem_kernel<<<16384, 128>>>(m1, mem_b1, ln1_g, ln1_b, nullptr, m2a, 1);
    gemm_p_kernel<true><<<dim3(1,128), blk, GSM>>>(m2a, mem_W2, m1, 16384, 128, 128);
    ln_mem_kernel<<<16384, 128>>>(m1, mem_b2, ln2_g, ln2_b, mstate, m2, 0);

    // ---- fused q|k|v projection + retrieved k|v
    gemm_p_kernel<true><<<dim3(24,128), blk, GSM>>>(x,  Wall, qkv, 16384, 3072, 1024);
    gemm_p_kernel<true><<<dim3(16,128), blk, GSM>>>(m2, Wkrv, kvr, 16384, 2048, 128);

    // ---- attention
    attn_kernel<<<dim3(256, 8), 256, ATTN_SMEM>>>(qkv, kvr, kp, vp,
                                                  mha_bq, mha_bk, bkr, mha_bv, bvr, A3);

    // ---- output path
    gemm_p_kernel<true><<<dim3(8,128), blk, GSM>>>(A3, mha_Wo, A4, 16384, 1024, 1024);
    biasln_c_kernel<<<16384, 256>>>(A4, mha_bo, gn_g, gn_b, A5);
    gemm_p_kernel<true><<<dim3(8,128), blk, GSM>>>(A5, gate_W, qkv, 16384, 1024, 1024);
    e2_kernel<<<8192, 256>>>(qkv, gate_b, A4, x, A5);
    gemm_p_kernel<true><<<dim3(8,128), blk, GSM>>>(A5, out_W, out, 16384, 1024, 1024);
    add_bias_kernel<<<8192, 256>>>(out, out_b);
}

// round 5
// speedup vs baseline: 6.3387x; 2.6982x over previous
#include <cuda_runtime.h>
#include <cuda_fp16.h>
#include <mma.h>
#include <cstdint>

using namespace nvcuda;

// B=4, L=4096, C=1024, M=128, P=4, S=64, H=8, hd=128
// NSEG=256, TOKS=16384, context T=132

__device__ float d_scratch[162100000ull];

__device__ __forceinline__ void cp16(uint32_t s, const void* g) {
    asm volatile("cp.async.cg.shared.global [%0], [%1], 16;\n" :: "r"(s), "l"(g) : "memory");
}

// ===========================================================================
// fp16 pipelined GEMM: C[M,N](f32) = Ah[M,K] @ Wh^T,  Wh=[N,K] halves.
// 128x128 tile, Ktile 64, 4 stages. smem = 2*4*9216 halves = 147456 B.
// ===========================================================================
#define HLD 72
#define HSTS 9216
#define GSM 147456

__device__ __forceinline__ void load_tile_h(const __half* Ag0, const __half* Wg0,
                                            int K, int it, __half* As, __half* Bs, int tid)
{
    const __half* Ag = Ag0 + it*64;
    const __half* Wg = Wg0 + it*64;
    uint32_t sA = (uint32_t)__cvta_generic_to_shared(As);
    uint32_t sB = (uint32_t)__cvta_generic_to_shared(Bs);
    #pragma unroll
    for (int i = 0; i < 4; i++) {
        int ch = tid + i*256;
        int r = ch >> 3, c = (ch & 7) << 3;
        cp16(sA + (uint32_t)(r*HLD + c)*2u, Ag + (size_t)r*K + c);
        cp16(sB + (uint32_t)(r*HLD + c)*2u, Wg + (size_t)r*K + c);
    }
}

__global__ __launch_bounds__(256)
void gemm_h_kernel(const __half* __restrict__ A, const __half* __restrict__ W,
                   float* __restrict__ Cout, int M, int N, int K)
{
    extern __shared__ __align__(16) __half smh[];
    __half* As = smh;
    __half* Bs = smh + 4*HSTS;

    const int tid  = threadIdx.x;
    const int warp = tid >> 5;
    const int wm   = warp & 3;
    const int wn   = warp >> 2;
    const int m0   = blockIdx.y * 128;
    const int n0   = blockIdx.x * 128;
    const int nk   = K >> 6;

    const __half* Ag0 = A + (size_t)m0*K;
    const __half* Wg0 = W + (size_t)n0*K;

    wmma::fragment<wmma::accumulator,16,16,16,float> cf[2][4];
    #pragma unroll
    for (int i = 0; i < 2; i++)
        #pragma unroll
        for (int j = 0; j < 4; j++)
            wmma::fill_fragment(cf[i][j], 0.0f);

    #pragma unroll
    for (int s = 0; s < 3; s++) {
        if (s < nk) load_tile_h(Ag0, Wg0, K, s, As + s*HSTS, Bs + s*HSTS, tid);
        asm volatile("cp.async.commit_group;\n" ::: "memory");
    }

    for (int it = 0; it < nk; it++) {
        if (it + 3 < nk) {
            int slot = (it + 3) & 3;
            load_tile_h(Ag0, Wg0, K, it + 3, As + slot*HSTS, Bs + slot*HSTS, tid);
        }
        asm volatile("cp.async.commit_group;\n" ::: "memory");
        asm volatile("cp.async.wait_group 3;\n" ::: "memory");
        __syncthreads();

        const __half* Ab = As + (it & 3)*HSTS;
        const __half* Bb = Bs + (it & 3)*HSTS;
        #pragma unroll
        for (int kk = 0; kk < 64; kk += 16) {
            wmma::fragment<wmma::matrix_a,16,16,16,__half,wmma::row_major> af[2];
            wmma::fragment<wmma::matrix_b,16,16,16,__half,wmma::col_major> bf[4];
            #pragma unroll
            for (int i = 0; i < 2; i++)
                wmma::load_matrix_sync(af[i], Ab + (wm*32 + i*16)*HLD + kk, HLD);
            #pragma unroll
            for (int j = 0; j < 4; j++)
                wmma::load_matrix_sync(bf[j], Bb + (wn*64 + j*16)*HLD + kk, HLD);
            #pragma unroll
            for (int i = 0; i < 2; i++)
                #pragma unroll
                for (int j = 0; j < 4; j++)
                    wmma::mma_sync(cf[i][j], af[i], bf[j], cf[i][j]);
        }
        __syncthreads();
    }

    #pragma unroll
    for (int i = 0; i < 2; i++)
        #pragma unroll
        for (int j = 0; j < 4; j++)
            wmma::store_matrix_sync(&Cout[(size_t)(m0 + wm*32 + i*16)*N + n0 + wn*64 + j*16],
                                    cf[i][j], N, wmma::mem_row_major);
}

// ===========================================================================
// fp32/tf32 pipelined GEMM body for weight prep: C = A @ B, B=[K,N] row-major
// ===========================================================================
#define STRIDE_S 4608

__device__ void gemm32_body(const float* __restrict__ A, const float* __restrict__ B,
                            float* __restrict__ C, int N, int K,
                            int am0, int n0, int cm0)
{
    extern __shared__ __align__(16) float sm[];
    float* As = sm;
    float* Bs = sm + 4*STRIDE_S;

    const int tid  = threadIdx.x;
    const int warp = tid >> 5;
    const int wm   = warp & 3;
    const int wn   = warp >> 2;
    const int nk   = K >> 5;

    wmma::fragment<wmma::accumulator,16,16,8,float> cf[2][4];
    #pragma unroll
    for (int i = 0; i < 2; i++)
        #pragma unroll
        for (int j = 0; j < 4; j++)
            wmma::fill_fragment(cf[i][j], 0.0f);

    auto load32 = [&](int it, float* Asb, float* Bsb) {
        const float* Ag = A + (size_t)am0*K + it*32;
        const float* Bg = B + (size_t)(it*32)*N + n0;
        uint32_t sA = (uint32_t)__cvta_generic_to_shared(Asb);
        uint32_t sB = (uint32_t)__cvta_generic_to_shared(Bsb);
        #pragma unroll
        for (int i = 0; i < 4; i++) {
            int ch = tid + i*256;
            int r = ch >> 3, c = (ch & 7) << 2;
            cp16(sA + (uint32_t)(r*36 + c)*4u, Ag + (size_t)r*K + c);
            int kk = ch >> 5, c2 = (ch & 31) << 2;
            cp16(sB + (uint32_t)(kk*132 + c2)*4u, Bg + (size_t)kk*N + c2);
        }
    };

    #pragma unroll
    for (int s = 0; s < 3; s++) {
        if (s < nk) load32(s, As + s*STRIDE_S, Bs + s*STRIDE_S);
        asm volatile("cp.async.commit_group;\n" ::: "memory");
    }

    for (int it = 0; it < nk; it++) {
        if (it + 3 < nk) {
            int slot = (it + 3) & 3;
            load32(it + 3, As + slot*STRIDE_S, Bs + slot*STRIDE_S);
        }
        asm volatile("cp.async.commit_group;\n" ::: "memory");
        asm volatile("cp.async.wait_group 3;\n" ::: "memory");
        __syncthreads();

        const float* Ab = As + (it & 3)*STRIDE_S;
        const float* Bb = Bs + (it & 3)*STRIDE_S;
        #pragma unroll
        for (int kk = 0; kk < 32; kk += 8) {
            wmma::fragment<wmma::matrix_a,16,16,8,wmma::precision::tf32,wmma::row_major> af[2];
            wmma::fragment<wmma::matrix_b,16,16,8,wmma::precision::tf32,wmma::row_major> bf[4];
            #pragma unroll
            for (int i = 0; i < 2; i++) {
                wmma::load_matrix_sync(af[i], Ab + (wm*32 + i*16)*36 + kk, 36);
                #pragma unroll
                for (int t = 0; t < af[i].num_elements; t++)
                    af[i].x[t] = wmma::__float_to_tf32(af[i].x[t]);
            }
            #pragma unroll
            for (int j = 0; j < 4; j++) {
                wmma::load_matrix_sync(bf[j], Bb + kk*132 + wn*64 + j*16, 132);
                #pragma unroll
                for (int t = 0; t < bf[j].num_elements; t++)
                    bf[j].x[t] = wmma::__float_to_tf32(bf[j].x[t]);
            }
            #pragma unroll
            for (int i = 0; i < 2; i++)
                #pragma unroll
                for (int j = 0; j < 4; j++)
                    wmma::mma_sync(cf[i][j], af[i], bf[j], cf[i][j]);
        }
        __syncthreads();
    }

    #pragma unroll
    for (int i = 0; i < 2; i++)
        #pragma unroll
        for (int j = 0; j < 4; j++)
            wmma::store_matrix_sync(&C[(size_t)(cm0 + wm*32 + i*16)*N + n0 + wn*64 + j*16],
                                    cf[i][j], N, wmma::mem_row_major);
}

// Wall (3x 1024^3) + W1q (128x1024x1024) in one launch: grid (8, 25)
__global__ __launch_bounds__(256)
void wall_prep_kernel(const float* mWq, const float* mWk, const float* mWv,
                      const float* memW1,
                      const float* Wq, const float* Wk, const float* Wv,
                      float* WallS, float* W1qS)
{
    int by = blockIdx.y;
    const float *A, *B; float* Cb; int am0;
    if (by < 8)       { A = mWq;   B = Wq; Cb = WallS;            am0 = by*128; }
    else if (by < 16) { A = mWk;   B = Wk; Cb = WallS + 1048576;  am0 = (by-8)*128; }
    else if (by < 24) { A = mWv;   B = Wv; Cb = WallS + 2097152;  am0 = (by-16)*128; }
    else              { A = memW1; B = Wq; Cb = W1qS;             am0 = 0; }
    gemm32_body(A, B, Cb, 1024, 1024, am0, blockIdx.x*128, am0);
}

// Wkrv = [WkK; WvV] @ mem_oW : grid (1, 16)
__global__ __launch_bounds__(256)
void wkrv_prep_kernel(const float* WallS, const float* mem_oW, float* WkrvS)
{
    int by = blockIdx.y;
    const float* A = (by < 8) ? (WallS + 1048576) : (WallS + 2097152);
    int am0 = (by & 7)*128;
    gemm32_body(A, mem_oW, WkrvS, 128, 1024, am0, 0, by*128);
}

// ===========================================================================
// elementwise / small kernels
// ===========================================================================
__global__ __launch_bounds__(256)
void f2h_kernel(const float* __restrict__ in, __half* __restrict__ out, size_t n)
{
    for (size_t i = ((size_t)blockIdx.x*blockDim.x + threadIdx.x)*4; i < n;
         i += (size_t)gridDim.x*blockDim.x*4) {
        float4 v = *reinterpret_cast<const float4*>(in + i);
        __half2* o = reinterpret_cast<__half2*>(out + i);
        o[0] = __floats2half2_rn(v.x, v.y);
        o[1] = __floats2half2_rn(v.z, v.w);
    }
}

__global__ __launch_bounds__(128)
void ln_mem_kernel(const float* __restrict__ pre, const float* __restrict__ bias,
                   const float* __restrict__ g, const float* __restrict__ b,
                   const float* __restrict__ mstate, __half* __restrict__ out, int do_silu)
{
    int r = blockIdx.x, t = threadIdx.x;
    float v = pre[(size_t)r*128 + t] + bias[t];
    if (do_silu) v = v / (1.0f + __expf(-v));

    float s = v, q = v*v;
    #pragma unroll
    for (int o = 16; o; o >>= 1) {
        s += __shfl_xor_sync(0xffffffffu, s, o);
        q += __shfl_xor_sync(0xffffffffu, q, o);
    }
    __shared__ float red[8];
    if ((t & 31) == 0) { red[t>>5] = s; red[4 + (t>>5)] = q; }
    __syncthreads();
    float S = red[0]+red[1]+red[2]+red[3];
    float Q = red[4]+red[5]+red[6]+red[7];
    float mu  = S * (1.0f/128.0f);
    float var = Q * (1.0f/128.0f) - mu*mu;
    float o = g[t]*(v - mu)*rsqrtf(var + 1e-5f) + b[t];
    if (mstate) o += mstate[t];
    out[(size_t)r*128 + t] = __float2half(o);
}

__global__ __launch_bounds__(256)
void biasln_c_kernel(float* __restrict__ a, const float* __restrict__ bo,
                     const float* __restrict__ g, const float* __restrict__ b,
                     __half* __restrict__ lo)
{
    size_t base = (size_t)blockIdx.x * 1024;
    int t = threadIdx.x;
    float4 v  = *reinterpret_cast<float4*>(a + base + t*4);
    float4 bb = *reinterpret_cast<const float4*>(bo + t*4);
    v.x += bb.x; v.y += bb.y; v.z += bb.z; v.w += bb.w;
    *reinterpret_cast<float4*>(a + base + t*4) = v;

    float s = v.x + v.y + v.z + v.w;
    float q = v.x*v.x + v.y*v.y + v.z*v.z + v.w*v.w;
    #pragma unroll
    for (int o = 16; o; o >>= 1) {
        s += __shfl_xor_sync(0xffffffffu, s, o);
        q += __shfl_xor_sync(0xffffffffu, q, o);
    }
    __shared__ float red[16];
    if ((t & 31) == 0) { red[t>>5] = s; red[8 + (t>>5)] = q; }
    __syncthreads();
    float S = 0.f, Q = 0.f;
    #pragma unroll
    for (int i = 0; i < 8; i++) { S += red[i]; Q += red[8+i]; }
    float mu  = S * (1.0f/1024.0f);
    float var = Q * (1.0f/1024.0f) - mu*mu;
    float rs  = rsqrtf(var + 1e-5f);

    float4 gg = *reinterpret_cast<const float4*>(g + t*4);
    float4 b2 = *reinterpret_cast<const float4*>(b + t*4);
    __half2* o = reinterpret_cast<__half2*>(lo + base + t*4);
    o[0] = __floats2half2_rn(gg.x*(v.x - mu)*rs + b2.x, gg.y*(v.y - mu)*rs + b2.y);
    o[1] = __floats2half2_rn(gg.z*(v.z - mu)*rs + b2.z, gg.w*(v.w - mu)*rs + b2.w);
}

__global__ __launch_bounds__(256)
void fuse_bias_kernel(const float* __restrict__ WkK, const float* __restrict__ WvV,
                      const float* __restrict__ mob,
                      const float* __restrict__ bk, const float* __restrict__ bv,
                      float* __restrict__ bkr, float* __restrict__ bvr)
{
    int i = blockIdx.x & 1023;
    bool isv = blockIdx.x >= 1024;
    const float* W = isv ? WvV : WkK;
    float s = 0.f;
    for (int k = threadIdx.x; k < 1024; k += 256) s += W[(size_t)i*1024 + k] * mob[k];
    #pragma unroll
    for (int o = 16; o; o >>= 1) s += __shfl_xor_sync(0xffffffffu, s, o);
    __shared__ float red[8];
    if ((threadIdx.x & 31) == 0) red[threadIdx.x >> 5] = s;
    __syncthreads();
    if (threadIdx.x == 0) {
        float S = 0.f;
        #pragma unroll
        for (int w = 0; w < 8; w++) S += red[w];
        (isv ? bvr : bkr)[i] = S + (isv ? bv : bk)[i];
    }
}

__global__ __launch_bounds__(256)
void pm_proj_kernel(const float* __restrict__ pm,
                    const float* __restrict__ WkK, const float* __restrict__ WvV,
                    const float* __restrict__ bk, const float* __restrict__ bv,
                    float* __restrict__ kp, float* __restrict__ vp)
{
    int id  = blockIdx.x;
    bool isv = id >= 4096;
    int p = (id & 4095) >> 10;
    int i = id & 1023;
    const float* W = isv ? WvV : WkK;
    float s = 0.f;
    for (int k = threadIdx.x; k < 1024; k += 256) s += pm[p*1024 + k] * W[(size_t)i*1024 + k];
    #pragma unroll
    for (int o = 16; o; o >>= 1) s += __shfl_xor_sync(0xffffffffu, s, o);
    __shared__ float red[8];
    if ((threadIdx.x & 31) == 0) red[threadIdx.x >> 5] = s;
    __syncthreads();
    if (threadIdx.x == 0) {
        float S = 0.f;
        #pragma unroll
        for (int w = 0; w < 8; w++) S += red[w];
        (isv ? vp : kp)[p*1024 + i] = S + (isv ? bv : bk)[i];
    }
}

// ===========================================================================
// fp16 tensor-core attention: block per (segment, head); 8 warps
// smem: ps f32[64][148] | qsh h[64][136] | ksh h[144][136] | vsh h[144][136] | ph h[64][152]
// ===========================================================================
#define PS_LD 148
#define QK_LD 136
#define PH_LD 152
#define ATTN_SMEM (64*PS_LD*4 + (64*QK_LD + 144*QK_LD + 144*QK_LD + 64*PH_LD)*2)

__global__ __launch_bounds__(256)
void attn_kernel(const float* __restrict__ qkv,
                 const float* __restrict__ kvr,
                 const float* __restrict__ kp, const float* __restrict__ vp,
                 const float* __restrict__ bq, const float* __restrict__ bk,
                 const float* __restrict__ bkr,
                 const float* __restrict__ bv, const float* __restrict__ bvr,
                 float* __restrict__ out)
{
    extern __shared__ __align__(16) float sm[];
    float*  ps  = sm;                                  // 64*148 f32
    __half* qsh = reinterpret_cast<__half*>(sm + 64*PS_LD);
    __half* ksh = qsh + 64*QK_LD;
    __half* vsh = ksh + 144*QK_LD;
    __half* ph  = vsh + 144*QK_LD;

    const int seg  = blockIdx.x;
    const int h    = blockIdx.y;
    const int tid  = threadIdx.x;
    const int warp = tid >> 5;
    const int lane = tid & 31;
    const int c0   = h * 128;
    const float scale = 0.08838834764831845f;   // 1/sqrt(128)

    // q (+bq)*scale -> half
    for (int i = tid; i < 64*32; i += 256) {
        int r = i >> 5, c4 = (i & 31) << 2;
        float4 v = *reinterpret_cast<const float4*>(qkv + (size_t)(seg*64 + r)*3072 + c0 + c4);
        float4 b = *reinterpret_cast<const float4*>(bq + c0 + c4);
        __half* d = qsh + r*QK_LD + c4;
        d[0] = __float2half((v.x + b.x)*scale); d[1] = __float2half((v.y + b.y)*scale);
        d[2] = __float2half((v.z + b.z)*scale); d[3] = __float2half((v.w + b.w)*scale);
    }
    // k rows (144; >=132 zero)
    for (int i = tid; i < 144*32; i += 256) {
        int r = i >> 5, c4 = (i & 31) << 2;
        float4 v = {0,0,0,0}, b = {0,0,0,0};
        if (r < 64) {
            v = *reinterpret_cast<const float4*>(kvr + (size_t)(seg*64 + r)*2048 + c0 + c4);
            b = *reinterpret_cast<const float4*>(bkr + c0 + c4);
        } else if (r < 68) {
            v = *reinterpret_cast<const float4*>(kp + (size_t)(r - 64)*1024 + c0 + c4);
        } else if (r < 132) {
            v = *reinterpret_cast<const float4*>(qkv + (size_t)(seg*64 + r - 68)*3072 + 1024 + c0 + c4);
            b = *reinterpret_cast<const float4*>(bk + c0 + c4);
        }
        __half* d = ksh + r*QK_LD + c4;
        d[0] = __float2half(v.x + b.x); d[1] = __float2half(v.y + b.y);
        d[2] = __float2half(v.z + b.z); d[3] = __float2half(v.w + b.w);
    }
    // v rows (144; >=132 zero)
    for (int i = tid; i < 144*32; i += 256) {
        int r = i >> 5, c4 = (i & 31) << 2;
        float4 v = {0,0,0,0}, b = {0,0,0,0};
        if (r < 64) {
            v = *reinterpret_cast<const float4*>(kvr + (size_t)(seg*64 + r)*2048 + 1024 + c0 + c4);
            b = *reinterpret_cast<const float4*>(bvr + c0 + c4);
        } else if (r < 68) {
            v = *reinterpret_cast<const float4*>(vp + (size_t)(r - 64)*1024 + c0 + c4);
        } else if (r < 132) {
            v = *reinterpret_cast<const float4*>(qkv + (size_t)(seg*64 + r - 68)*3072 + 2048 + c0 + c4);
            b = *reinterpret_cast<const float4*>(bv + c0 + c4);
        }
        __half* d = vsh + r*QK_LD + c4;
        d[0] = __float2half(v.x + b.x); d[1] = __float2half(v.y + b.y);
        d[2] = __float2half(v.z + b.z); d[3] = __float2half(v.w + b.w);
    }
    __syncthreads();

    // scores = q @ k^T : 64 x 144 (4x9 tiles of 16x16), K=128
    for (int t = warp; t < 36; t += 8) {
        int ms = (t / 9) * 16;
        int ns = (t % 9) * 16;
        wmma::fragment<wmma::accumulator,16,16,16,float> acc;
        wmma::fill_fragment(acc, 0.0f);
        #pragma unroll
        for (int kk = 0; kk < 128; kk += 16) {
            wmma::fragment<wmma::matrix_a,16,16,16,__half,wmma::row_major> af;
            wmma::fragment<wmma::matrix_b,16,16,16,__half,wmma::col_major> bf;
            wmma::load_matrix_sync(af, qsh + ms*QK_LD + kk, QK_LD);
            wmma::load_matrix_sync(bf, ksh + ns*QK_LD + kk, QK_LD);
            wmma::mma_sync(acc, af, bf, acc);
        }
        wmma::store_matrix_sync(ps + ms*PS_LD + ns, acc, PS_LD, wmma::mem_row_major);
    }
    __syncthreads();

    // softmax rows (132 valid cols), write normalized half probs to ph
    for (int r = warp*8; r < warp*8 + 8; r++) {
        float* row = ps + r*PS_LD;
        float m = -1e30f;
        for (int c = lane; c < 132; c += 32) m = fmaxf(m, row[c]);
        #pragma unroll
        for (int o = 16; o; o >>= 1) m = fmaxf(m, __shfl_xor_sync(0xffffffffu, m, o));
        float s = 0.f;
        for (int c = lane; c < 132; c += 32) { float e = __expf(row[c] - m); row[c] = e; s += e; }
        #pragma unroll
        for (int o = 16; o; o >>= 1) s += __shfl_xor_sync(0xffffffffu, s, o);
        float inv = 1.0f / s;
        for (int c = lane; c < 132; c += 32) ph[r*PH_LD + c] = __float2half(row[c]*inv);
        if (lane < 20) ph[r*PH_LD + 132 + lane] = __float2half(0.0f);
    }
    __syncthreads();

    // out = p @ v : 64 x 128 (4x8 tiles), k=144
    for (int t = warp; t < 32; t += 8) {
        int ms = (t >> 3) * 16;
        int ds = (t & 7) * 16;
        wmma::fragment<wmma::accumulator,16,16,16,float> acc;
        wmma::fill_fragment(acc, 0.0f);
        #pragma unroll
        for (int kk = 0; kk < 144; kk += 16) {
            wmma::fragment<wmma::matrix_a,16,16,16,__half,wmma::row_major> af;
            wmma::fragment<wmma::matrix_b,16,16,16,__half,wmma::row_major> bf;
            wmma::load_matrix_sync(af, ph + ms*PH_LD + kk, PH_LD);
            wmma::load_matrix_sync(bf, vsh + kk*QK_LD + ds, QK_LD);
            wmma::mma_sync(acc, af, bf, acc);
        }
        wmma::store_matrix_sync(&out[(size_t)(seg*64 + ms)*1024 + c0 + ds], acc, 1024,
                                wmma::mem_row_major);
    }
}

// gate blend: u = sigmoid(gpre + gate_b) * attn_biased + x  (half out)
__global__ __launch_bounds__(256)
void e2_kernel(const float* __restrict__ gpre, const float* __restrict__ gb,
               const float* __restrict__ attnb, const float* __restrict__ x,
               __half* __restrict__ u)
{
    for (size_t idx = (size_t)blockIdx.x*blockDim.x + threadIdx.x;
         idx < 16777216ull; idx += (size_t)gridDim.x*blockDim.x) {
        int c = (int)(idx & 1023);
        float g = 1.0f / (1.0f + __expf(-(gpre[idx] + gb[c])));
        u[idx] = __float2half(g * attnb[idx] + x[idx]);
    }
}

__global__ __launch_bounds__(256)
void add_bias_kernel(float* __restrict__ out, const float* __restrict__ ob)
{
    for (size_t idx = (size_t)blockIdx.x*blockDim.x + threadIdx.x;
         idx < 16777216ull; idx += (size_t)gridDim.x*blockDim.x)
        out[idx] += ob[idx & 1023];
}

// ===========================================================================
extern "C" void kernel_launch(void* const* d_in, const int* in_sizes, int n_in,
                              void* d_out, int out_size)
{
    const float* x      = (const float*)d_in[0];
    const float* pm     = (const float*)d_in[1];
    const float* Wq     = (const float*)d_in[2];
    const float* Wk     = (const float*)d_in[3];
    const float* Wv     = (const float*)d_in[4];
    const float* mem_W1 = (const float*)d_in[5];
    const float* mem_b1 = (const float*)d_in[6];
    const float* ln1_g  = (const float*)d_in[7];
    const float* ln1_b  = (const float*)d_in[8];
    const float* mem_W2 = (const float*)d_in[9];
    const float* mem_b2 = (const float*)d_in[10];
    const float* ln2_g  = (const float*)d_in[11];
    const float* ln2_b  = (const float*)d_in[12];
    const float* mem_oW = (const float*)d_in[13];
    const float* mem_ob = (const float*)d_in[14];
    const float* mstate = (const float*)d_in[15];
    const float* mha_Wq = (const float*)d_in[16];
    const float* mha_bq = (const float*)d_in[17];
    const float* mha_Wk = (const float*)d_in[18];
    const float* mha_bk = (const float*)d_in[19];
    const float* mha_Wv = (const float*)d_in[20];
    const float* mha_bv = (const float*)d_in[21];
    const float* mha_Wo = (const float*)d_in[22];
    const float* mha_bo = (const float*)d_in[23];
    const float* gn_g   = (const float*)d_in[24];
    const float* gn_b   = (const float*)d_in[25];
    const float* gate_W = (const float*)d_in[26];
    const float* gate_b = (const float*)d_in[27];
    const float* out_W  = (const float*)d_in[28];
    const float* out_b  = (const float*)d_in[29];
    float* out = (float*)d_out;

    void* sp; cudaGetSymbolAddress(&sp, d_scratch);
    float* S0 = (float*)sp;
    float* qkv   = S0;                                  // [16384][3072] f32
    float* kvr   = qkv   + 50331648ull;                 // [16384][2048] f32
    float* A3    = kvr   + 33554432ull;                 // attn out f32
    float* A4    = A3    + 16777216ull;                 // Wo out f32
    float* m1    = A4    + 16777216ull;                 // [16384][128] f32
    float* WallS = m1    + 2097152ull;                  // [3072][1024] f32 staging
    float* WkrvS = WallS + 3145728ull;                  // [2048][128]
    float* W1qS  = WkrvS + 262144ull;                   // [128][1024]
    float* hbase = W1qS  + 131072ull;
    __half* xh    = (__half*)hbase;                     // 16777216 h
    __half* A3h   = xh    + 16777216ull;
    __half* A5h   = A3h   + 16777216ull;
    __half* uh    = A5h   + 16777216ull;
    __half* m2ah  = uh    + 16777216ull;                // [16384][128] h
    __half* m2h   = m2ah  + 2097152ull;
    __half* Wallh = m2h   + 2097152ull;                 // 3145728 h
    __half* Wkrvh = Wallh + 3145728ull;                 // 262144 h (contiguous w/ Wallh)
    __half* W1qh  = Wkrvh + 262144ull;                  // 131072 h
    __half* W2h   = W1qh  + 131072ull;                  // 16384 h
    __half* Woh   = W2h   + 16384ull;
    __half* gateh = Woh   + 1048576ull;
    __half* outh  = gateh + 1048576ull;
    float* kp  = (float*)(outh + 1048576ull);
    float* vp  = kp + 4096;
    float* bkr = vp + 4096;
    float* bvr = bkr + 1024;
    float* WkK = WallS + 1048576ull;
    float* WvV = WallS + 2097152ull;

    cudaFuncSetAttribute(gemm_h_kernel,    cudaFuncAttributeMaxDynamicSharedMemorySize, GSM);
    cudaFuncSetAttribute(wall_prep_kernel, cudaFuncAttributeMaxDynamicSharedMemorySize, GSM);
    cudaFuncSetAttribute(wkrv_prep_kernel, cudaFuncAttributeMaxDynamicSharedMemorySize, GSM);
    cudaFuncSetAttribute(attn_kernel,      cudaFuncAttributeMaxDynamicSharedMemorySize, ATTN_SMEM);

    dim3 blk(256);

    // ---- converts that gate nothing else first
    f2h_kernel<<<4096, 256>>>(x, xh, 16777216ull);
    f2h_kernel<<<512,  256>>>(mem_W2, W2h, 16384ull);
    f2h_kernel<<<2048, 256>>>(mha_Wo, Woh, 1048576ull);
    f2h_kernel<<<2048, 256>>>(gate_W, gateh, 1048576ull);
    f2h_kernel<<<2048, 256>>>(out_W, outh, 1048576ull);

    // ---- weight prep (fp32 tf32) + convert to half
    wall_prep_kernel<<<dim3(8,25), blk, GSM>>>(mha_Wq, mha_Wk, mha_Wv, mem_W1,
                                               Wq, Wk, Wv, WallS, W1qS);
    wkrv_prep_kernel<<<dim3(1,16), blk, GSM>>>(WallS, mem_oW, WkrvS);
    f2h_kernel<<<4096, 256>>>(WallS, Wallh, 3538944ull);  // WallS|WkrvS|W1qS contiguous
    fuse_bias_kernel<<<2048, 256>>>(WkK, WvV, mem_ob, mha_bk, mha_bv, bkr, bvr);
    pm_proj_kernel<<<8192, 256>>>(pm, WkK, WvV, mha_bk, mha_bv, kp, vp);

    // ---- memory net
    gemm_h_kernel<<<dim3(1,128), blk, GSM>>>(xh, W1qh, m1, 16384, 128, 1024);
    ln_mem_kernel<<<16384, 128>>>(m1, mem_b1, ln1_g, ln1_b, nullptr, m2ah, 1);
    gemm_h_kernel<<<dim3(1,128), blk, GSM>>>(m2ah, W2h, m1, 16384, 128, 128);
    ln_mem_kernel<<<16384, 128>>>(m1, mem_b2, ln2_g, ln2_b, mstate, m2h, 0);

    // ---- fused q|k|v projection + retrieved k|v
    gemm_h_kernel<<<dim3(24,128), blk, GSM>>>(xh,  Wallh, qkv, 16384, 3072, 1024);
    gemm_h_kernel<<<dim3(16,128), blk, GSM>>>(m2h, Wkrvh, kvr, 16384, 2048, 128);

    // ---- attention
    attn_kernel<<<dim3(256, 8), 256, ATTN_SMEM>>>(qkv, kvr, kp, vp,
                                                  mha_bq, mha_bk, bkr, mha_bv, bvr, A3);
    f2h_kernel<<<4096, 256>>>(A3, A3h, 16777216ull);

    // ---- output path
    gemm_h_kernel<<<dim3(8,128), blk, GSM>>>(A3h, Woh, A4, 16384, 1024, 1024);
    biasln_c_kernel<<<16384, 256>>>(A4, mha_bo, gn_g, gn_b, A5h);
    gemm_h_kernel<<<dim3(8,128), blk, GSM>>>(A5h, gateh, qkv, 16384, 1024, 1024);
    e2_kernel<<<8192, 256>>>(qkv, gate_b, A4, x, uh);
    gemm_h_kernel<<<dim3(8,128), blk, GSM>>>(uh, outh, out, 16384, 1024, 1024);
    add_bias_kernel<<<8192, 256>>>(out, out_b);
}

// round 6
// speedup vs baseline: 6.6310x; 1.0461x over previous
#include <cuda_runtime.h>
#include <cuda_fp16.h>
#include <mma.h>
#include <cstdint>

using namespace nvcuda;

// B=4, L=4096, C=1024, M=128, P=4, S=64, H=8, hd=128
// NSEG=256, TOKS=16384, context T=132

__device__ float d_scratch[162100000ull];

__device__ __forceinline__ void cp16(uint32_t s, const void* g) {
    asm volatile("cp.async.cg.shared.global [%0], [%1], 16;\n" :: "r"(s), "l"(g) : "memory");
}

// ===========================================================================
// fp16 GEMM #1 (small-N path): 128x128 tile, Ktile 64, 4 stages, f32 out
// ===========================================================================
#define HLD 72
#define HSTS 9216
#define GSM 147456

__device__ __forceinline__ void load_tile_h(const __half* Ag0, const __half* Wg0,
                                            int K, int it, __half* As, __half* Bs, int tid)
{
    const __half* Ag = Ag0 + it*64;
    const __half* Wg = Wg0 + it*64;
    uint32_t sA = (uint32_t)__cvta_generic_to_shared(As);
    uint32_t sB = (uint32_t)__cvta_generic_to_shared(Bs);
    #pragma unroll
    for (int i = 0; i < 4; i++) {
        int ch = tid + i*256;
        int r = ch >> 3, c = (ch & 7) << 3;
        cp16(sA + (uint32_t)(r*HLD + c)*2u, Ag + (size_t)r*K + c);
        cp16(sB + (uint32_t)(r*HLD + c)*2u, Wg + (size_t)r*K + c);
    }
}

__global__ __launch_bounds__(256)
void gemm_h_kernel(const __half* __restrict__ A, const __half* __restrict__ W,
                   float* __restrict__ Cout, int M, int N, int K)
{
    extern __shared__ __align__(16) __half smh[];
    __half* As = smh;
    __half* Bs = smh + 4*HSTS;

    const int tid  = threadIdx.x;
    const int warp = tid >> 5;
    const int wm   = warp & 3;
    const int wn   = warp >> 2;
    const int m0   = blockIdx.y * 128;
    const int n0   = blockIdx.x * 128;
    const int nk   = K >> 6;

    const __half* Ag0 = A + (size_t)m0*K;
    const __half* Wg0 = W + (size_t)n0*K;

    wmma::fragment<wmma::accumulator,16,16,16,float> cf[2][4];
    #pragma unroll
    for (int i = 0; i < 2; i++)
        #pragma unroll
        for (int j = 0; j < 4; j++)
            wmma::fill_fragment(cf[i][j], 0.0f);

    #pragma unroll
    for (int s = 0; s < 3; s++) {
        if (s < nk) load_tile_h(Ag0, Wg0, K, s, As + s*HSTS, Bs + s*HSTS, tid);
        asm volatile("cp.async.commit_group;\n" ::: "memory");
    }

    for (int it = 0; it < nk; it++) {
        if (it + 3 < nk) {
            int slot = (it + 3) & 3;
            load_tile_h(Ag0, Wg0, K, it + 3, As + slot*HSTS, Bs + slot*HSTS, tid);
        }
        asm volatile("cp.async.commit_group;\n" ::: "memory");
        asm volatile("cp.async.wait_group 3;\n" ::: "memory");
        __syncthreads();

        const __half* Ab = As + (it & 3)*HSTS;
        const __half* Bb = Bs + (it & 3)*HSTS;
        #pragma unroll
        for (int kk = 0; kk < 64; kk += 16) {
            wmma::fragment<wmma::matrix_a,16,16,16,__half,wmma::row_major> af[2];
            wmma::fragment<wmma::matrix_b,16,16,16,__half,wmma::col_major> bf[4];
            #pragma unroll
            for (int i = 0; i < 2; i++)
                wmma::load_matrix_sync(af[i], Ab + (wm*32 + i*16)*HLD + kk, HLD);
            #pragma unroll
            for (int j = 0; j < 4; j++)
                wmma::load_matrix_sync(bf[j], Bb + (wn*64 + j*16)*HLD + kk, HLD);
            #pragma unroll
            for (int i = 0; i < 2; i++)
                #pragma unroll
                for (int j = 0; j < 4; j++)
                    wmma::mma_sync(cf[i][j], af[i], bf[j], cf[i][j]);
        }
        __syncthreads();
    }

    #pragma unroll
    for (int i = 0; i < 2; i++)
        #pragma unroll
        for (int j = 0; j < 4; j++)
            wmma::store_matrix_sync(&Cout[(size_t)(m0 + wm*32 + i*16)*N + n0 + wn*64 + j*16],
                                    cf[i][j], N, wmma::mem_row_major);
}

// ===========================================================================
// fp16 GEMM #2 (main path): 256x128 CTA tile, 64x64 warp tile, Ktile 32,
// 4 stages. Optional fp16 output and fused bias. smem = 122880 B.
// ===========================================================================
#define H2LD 40
#define H2_AS 10240
#define H2_BS 5120
#define GSM2 ((4*(H2_AS + H2_BS))*2)

__device__ __forceinline__ void load_tile_h2(const __half* Ag0, const __half* Wg0,
                                             int K, int it, __half* As, __half* Bs, int tid)
{
    const __half* Ag = Ag0 + it*32;
    const __half* Wg = Wg0 + it*32;
    uint32_t sA = (uint32_t)__cvta_generic_to_shared(As);
    uint32_t sB = (uint32_t)__cvta_generic_to_shared(Bs);
    #pragma unroll
    for (int i = 0; i < 4; i++) {
        int ch = tid + i*256;               // 0..1023 : A 256 rows x 4 chunks
        int r = ch >> 2, c = (ch & 3) << 3;
        cp16(sA + (uint32_t)(r*H2LD + c)*2u, Ag + (size_t)r*K + c);
    }
    #pragma unroll
    for (int i = 0; i < 2; i++) {
        int ch = tid + i*256;               // 0..511 : B 128 rows x 4 chunks
        int r = ch >> 2, c = (ch & 3) << 3;
        cp16(sB + (uint32_t)(r*H2LD + c)*2u, Wg + (size_t)r*K + c);
    }
}

template<bool HALF_OUT>
__global__ __launch_bounds__(256)
void gemm_h2_kernel(const __half* __restrict__ A, const __half* __restrict__ W,
                    void* __restrict__ Cout, const float* __restrict__ bias,
                    int M, int N, int K)
{
    extern __shared__ __align__(16) __half smh[];
    __half* As = smh;
    __half* Bs = smh + 4*H2_AS;

    const int tid  = threadIdx.x;
    const int warp = tid >> 5;
    const int lane = tid & 31;
    const int wm   = warp & 3;   // 4 m-groups of 64
    const int wn   = warp >> 2;  // 2 n-groups of 64
    const int m0   = blockIdx.y * 256;
    const int n0   = blockIdx.x * 128;
    const int nk   = K >> 5;

    const __half* Ag0 = A + (size_t)m0*K;
    const __half* Wg0 = W + (size_t)n0*K;

    wmma::fragment<wmma::accumulator,16,16,16,float> cf[4][4];
    #pragma unroll
    for (int i = 0; i < 4; i++)
        #pragma unroll
        for (int j = 0; j < 4; j++)
            wmma::fill_fragment(cf[i][j], 0.0f);

    #pragma unroll
    for (int s = 0; s < 3; s++) {
        if (s < nk) load_tile_h2(Ag0, Wg0, K, s, As + s*H2_AS, Bs + s*H2_BS, tid);
        asm volatile("cp.async.commit_group;\n" ::: "memory");
    }

    for (int it = 0; it < nk; it++) {
        if (it + 3 < nk) {
            int slot = (it + 3) & 3;
            load_tile_h2(Ag0, Wg0, K, it + 3, As + slot*H2_AS, Bs + slot*H2_BS, tid);
        }
        asm volatile("cp.async.commit_group;\n" ::: "memory");
        asm volatile("cp.async.wait_group 3;\n" ::: "memory");
        __syncthreads();

        const __half* Ab = As + (it & 3)*H2_AS;
        const __half* Bb = Bs + (it & 3)*H2_BS;
        #pragma unroll
        for (int kk = 0; kk < 32; kk += 16) {
            wmma::fragment<wmma::matrix_a,16,16,16,__half,wmma::row_major> af[4];
            wmma::fragment<wmma::matrix_b,16,16,16,__half,wmma::col_major> bf[4];
            #pragma unroll
            for (int i = 0; i < 4; i++)
                wmma::load_matrix_sync(af[i], Ab + (wm*64 + i*16)*H2LD + kk, H2LD);
            #pragma unroll
            for (int j = 0; j < 4; j++)
                wmma::load_matrix_sync(bf[j], Bb + (wn*64 + j*16)*H2LD + kk, H2LD);
            #pragma unroll
            for (int i = 0; i < 4; i++)
                #pragma unroll
                for (int j = 0; j < 4; j++)
                    wmma::mma_sync(cf[i][j], af[i], bf[j], cf[i][j]);
        }
        __syncthreads();
    }

    if (!HALF_OUT && bias == nullptr) {
        float* Cf = (float*)Cout;
        #pragma unroll
        for (int i = 0; i < 4; i++)
            #pragma unroll
            for (int j = 0; j < 4; j++)
                wmma::store_matrix_sync(&Cf[(size_t)(m0 + wm*64 + i*16)*N + n0 + wn*64 + j*16],
                                        cf[i][j], N, wmma::mem_row_major);
    } else {
        float* stage = reinterpret_cast<float*>(smh) + warp*256;   // 16x16 f32 per warp
        #pragma unroll
        for (int i = 0; i < 4; i++)
            #pragma unroll
            for (int j = 0; j < 4; j++) {
                wmma::store_matrix_sync(stage, cf[i][j], 16, wmma::mem_row_major);
                __syncwarp();
                int mb = m0 + wm*64 + i*16;
                int nb = n0 + wn*64 + j*16;
                #pragma unroll
                for (int e = lane; e < 256; e += 32) {
                    int rr = e >> 4, cc = e & 15;
                    float v = stage[e];
                    if (bias) v += bias[nb + cc];
                    if (HALF_OUT)
                        ((__half*)Cout)[(size_t)(mb + rr)*N + nb + cc] = __float2half(v);
                    else
                        ((float*)Cout)[(size_t)(mb + rr)*N + nb + cc] = v;
                }
                __syncwarp();
            }
    }
}

// ===========================================================================
// fp32/tf32 pipelined GEMM for weight prep: C = A @ B, B=[K,N] row-major
// ===========================================================================
#define STRIDE_S 4608

__device__ void gemm32_body(const float* __restrict__ A, const float* __restrict__ B,
                            float* __restrict__ C, int N, int K,
                            int am0, int n0, int cm0)
{
    extern __shared__ __align__(16) float sm[];
    float* As = sm;
    float* Bs = sm + 4*STRIDE_S;

    const int tid  = threadIdx.x;
    const int warp = tid >> 5;
    const int wm   = warp & 3;
    const int wn   = warp >> 2;
    const int nk   = K >> 5;

    wmma::fragment<wmma::accumulator,16,16,8,float> cf[2][4];
    #pragma unroll
    for (int i = 0; i < 2; i++)
        #pragma unroll
        for (int j = 0; j < 4; j++)
            wmma::fill_fragment(cf[i][j], 0.0f);

    auto load32 = [&](int it, float* Asb, float* Bsb) {
        const float* Ag = A + (size_t)am0*K + it*32;
        const float* Bg = B + (size_t)(it*32)*N + n0;
        uint32_t sA = (uint32_t)__cvta_generic_to_shared(Asb);
        uint32_t sB = (uint32_t)__cvta_generic_to_shared(Bsb);
        #pragma unroll
        for (int i = 0; i < 4; i++) {
            int ch = tid + i*256;
            int r = ch >> 3, c = (ch & 7) << 2;
            cp16(sA + (uint32_t)(r*36 + c)*4u, Ag + (size_t)r*K + c);
            int kk = ch >> 5, c2 = (ch & 31) << 2;
            cp16(sB + (uint32_t)(kk*132 + c2)*4u, Bg + (size_t)kk*N + c2);
        }
    };

    #pragma unroll
    for (int s = 0; s < 3; s++) {
        if (s < nk) load32(s, As + s*STRIDE_S, Bs + s*STRIDE_S);
        asm volatile("cp.async.commit_group;\n" ::: "memory");
    }

    for (int it = 0; it < nk; it++) {
        if (it + 3 < nk) {
            int slot = (it + 3) & 3;
            load32(it + 3, As + slot*STRIDE_S, Bs + slot*STRIDE_S);
        }
        asm volatile("cp.async.commit_group;\n" ::: "memory");
        asm volatile("cp.async.wait_group 3;\n" ::: "memory");
        __syncthreads();

        const float* Ab = As + (it & 3)*STRIDE_S;
        const float* Bb = Bs + (it & 3)*STRIDE_S;
        #pragma unroll
        for (int kk = 0; kk < 32; kk += 8) {
            wmma::fragment<wmma::matrix_a,16,16,8,wmma::precision::tf32,wmma::row_major> af[2];
            wmma::fragment<wmma::matrix_b,16,16,8,wmma::precision::tf32,wmma::row_major> bf[4];
            #pragma unroll
            for (int i = 0; i < 2; i++) {
                wmma::load_matrix_sync(af[i], Ab + (wm*32 + i*16)*36 + kk, 36);
                #pragma unroll
                for (int t = 0; t < af[i].num_elements; t++)
                    af[i].x[t] = wmma::__float_to_tf32(af[i].x[t]);
            }
            #pragma unroll
            for (int j = 0; j < 4; j++) {
                wmma::load_matrix_sync(bf[j], Bb + kk*132 + wn*64 + j*16, 132);
                #pragma unroll
                for (int t = 0; t < bf[j].num_elements; t++)
                    bf[j].x[t] = wmma::__float_to_tf32(bf[j].x[t]);
            }
            #pragma unroll
            for (int i = 0; i < 2; i++)
                #pragma unroll
                for (int j = 0; j < 4; j++)
                    wmma::mma_sync(cf[i][j], af[i], bf[j], cf[i][j]);
        }
        __syncthreads();
    }

    #pragma unroll
    for (int i = 0; i < 2; i++)
        #pragma unroll
        for (int j = 0; j < 4; j++)
            wmma::store_matrix_sync(&C[(size_t)(cm0 + wm*32 + i*16)*N + n0 + wn*64 + j*16],
                                    cf[i][j], N, wmma::mem_row_major);
}

__global__ __launch_bounds__(256)
void wall_prep_kernel(const float* mWq, const float* mWk, const float* mWv,
                      const float* memW1,
                      const float* Wq, const float* Wk, const float* Wv,
                      float* WallS, float* W1qS)
{
    int by = blockIdx.y;
    const float *A, *B; float* Cb; int am0;
    if (by < 8)       { A = mWq;   B = Wq; Cb = WallS;            am0 = by*128; }
    else if (by < 16) { A = mWk;   B = Wk; Cb = WallS + 1048576;  am0 = (by-8)*128; }
    else if (by < 24) { A = mWv;   B = Wv; Cb = WallS + 2097152;  am0 = (by-16)*128; }
    else              { A = memW1; B = Wq; Cb = W1qS;             am0 = 0; }
    gemm32_body(A, B, Cb, 1024, 1024, am0, blockIdx.x*128, am0);
}

__global__ __launch_bounds__(256)
void wkrv_prep_kernel(const float* WallS, const float* mem_oW, float* WkrvS)
{
    int by = blockIdx.y;
    const float* A = (by < 8) ? (WallS + 1048576) : (WallS + 2097152);
    int am0 = (by & 7)*128;
    gemm32_body(A, mem_oW, WkrvS, 128, 1024, am0, 0, by*128);
}

// ===========================================================================
// elementwise / small kernels
// ===========================================================================
__global__ __launch_bounds__(256)
void f2h_kernel(const float* __restrict__ in, __half* __restrict__ out, size_t n)
{
    for (size_t i = ((size_t)blockIdx.x*blockDim.x + threadIdx.x)*4; i < n;
         i += (size_t)gridDim.x*blockDim.x*4) {
        float4 v = *reinterpret_cast<const float4*>(in + i);
        __half2* o = reinterpret_cast<__half2*>(out + i);
        o[0] = __floats2half2_rn(v.x, v.y);
        o[1] = __floats2half2_rn(v.z, v.w);
    }
}

__global__ __launch_bounds__(128)
void ln_mem_kernel(const float* __restrict__ pre, const float* __restrict__ bias,
                   const float* __restrict__ g, const float* __restrict__ b,
                   const float* __restrict__ mstate, __half* __restrict__ out, int do_silu)
{
    int r = blockIdx.x, t = threadIdx.x;
    float v = pre[(size_t)r*128 + t] + bias[t];
    if (do_silu) v = v / (1.0f + __expf(-v));

    float s = v, q = v*v;
    #pragma unroll
    for (int o = 16; o; o >>= 1) {
        s += __shfl_xor_sync(0xffffffffu, s, o);
        q += __shfl_xor_sync(0xffffffffu, q, o);
    }
    __shared__ float red[8];
    if ((t & 31) == 0) { red[t>>5] = s; red[4 + (t>>5)] = q; }
    __syncthreads();
    float S = red[0]+red[1]+red[2]+red[3];
    float Q = red[4]+red[5]+red[6]+red[7];
    float mu  = S * (1.0f/128.0f);
    float var = Q * (1.0f/128.0f) - mu*mu;
    float o = g[t]*(v - mu)*rsqrtf(var + 1e-5f) + b[t];
    if (mstate) o += mstate[t];
    out[(size_t)r*128 + t] = __float2half(o);
}

__global__ __launch_bounds__(256)
void biasln_c_kernel(float* __restrict__ a, const float* __restrict__ bo,
                     const float* __restrict__ g, const float* __restrict__ b,
                     __half* __restrict__ lo)
{
    size_t base = (size_t)blockIdx.x * 1024;
    int t = threadIdx.x;
    float4 v  = *reinterpret_cast<float4*>(a + base + t*4);
    float4 bb = *reinterpret_cast<const float4*>(bo + t*4);
    v.x += bb.x; v.y += bb.y; v.z += bb.z; v.w += bb.w;
    *reinterpret_cast<float4*>(a + base + t*4) = v;

    float s = v.x + v.y + v.z + v.w;
    float q = v.x*v.x + v.y*v.y + v.z*v.z + v.w*v.w;
    #pragma unroll
    for (int o = 16; o; o >>= 1) {
        s += __shfl_xor_sync(0xffffffffu, s, o);
        q += __shfl_xor_sync(0xffffffffu, q, o);
    }
    __shared__ float red[16];
    if ((t & 31) == 0) { red[t>>5] = s; red[8 + (t>>5)] = q; }
    __syncthreads();
    float S = 0.f, Q = 0.f;
    #pragma unroll
    for (int i = 0; i < 8; i++) { S += red[i]; Q += red[8+i]; }
    float mu  = S * (1.0f/1024.0f);
    float var = Q * (1.0f/1024.0f) - mu*mu;
    float rs  = rsqrtf(var + 1e-5f);

    float4 gg = *reinterpret_cast<const float4*>(g + t*4);
    float4 b2 = *reinterpret_cast<const float4*>(b + t*4);
    __half2* o = reinterpret_cast<__half2*>(lo + base + t*4);
    o[0] = __floats2half2_rn(gg.x*(v.x - mu)*rs + b2.x, gg.y*(v.y - mu)*rs + b2.y);
    o[1] = __floats2half2_rn(gg.z*(v.z - mu)*rs + b2.z, gg.w*(v.w - mu)*rs + b2.w);
}

__global__ __launch_bounds__(256)
void fuse_bias_kernel(const float* __restrict__ WkK, const float* __restrict__ WvV,
                      const float* __restrict__ mob,
                      const float* __restrict__ bk, const float* __restrict__ bv,
                      float* __restrict__ bkr, float* __restrict__ bvr)
{
    int i = blockIdx.x & 1023;
    bool isv = blockIdx.x >= 1024;
    const float* W = isv ? WvV : WkK;
    float s = 0.f;
    for (int k = threadIdx.x; k < 1024; k += 256) s += W[(size_t)i*1024 + k] * mob[k];
    #pragma unroll
    for (int o = 16; o; o >>= 1) s += __shfl_xor_sync(0xffffffffu, s, o);
    __shared__ float red[8];
    if ((threadIdx.x & 31) == 0) red[threadIdx.x >> 5] = s;
    __syncthreads();
    if (threadIdx.x == 0) {
        float S = 0.f;
        #pragma unroll
        for (int w = 0; w < 8; w++) S += red[w];
        (isv ? bvr : bkr)[i] = S + (isv ? bv : bk)[i];
    }
}

__global__ __launch_bounds__(256)
void pm_proj_kernel(const float* __restrict__ pm,
                    const float* __restrict__ WkK, const float* __restrict__ WvV,
                    const float* __restrict__ bk, const float* __restrict__ bv,
                    float* __restrict__ kp, float* __restrict__ vp)
{
    int id  = blockIdx.x;
    bool isv = id >= 4096;
    int p = (id & 4095) >> 10;
    int i = id & 1023;
    const float* W = isv ? WvV : WkK;
    float s = 0.f;
    for (int k = threadIdx.x; k < 1024; k += 256) s += pm[p*1024 + k] * W[(size_t)i*1024 + k];
    #pragma unroll
    for (int o = 16; o; o >>= 1) s += __shfl_xor_sync(0xffffffffu, s, o);
    __shared__ float red[8];
    if ((threadIdx.x & 31) == 0) red[threadIdx.x >> 5] = s;
    __syncthreads();
    if (threadIdx.x == 0) {
        float S = 0.f;
        #pragma unroll
        for (int w = 0; w < 8; w++) S += red[w];
        (isv ? vp : kp)[p*1024 + i] = S + (isv ? bv : bk)[i];
    }
}

// ===========================================================================
// fp16 attention: block per (segment, head); 8 warps; half in, half out
// smem: ps f32[64][148] | qsh h[64][136] | ksh h[144][136] | vsh h[144][136] | ph h[64][152]
// ===========================================================================
#define PS_LD 148
#define QK_LD 136
#define PH_LD 152
#define ATTN_SMEM (64*PS_LD*4 + (64*QK_LD + 144*QK_LD + 144*QK_LD + 64*PH_LD)*2)

__global__ __launch_bounds__(256)
void attn_kernel(const __half* __restrict__ qkv,     // [16384][3072] h
                 const __half* __restrict__ kvr,     // [16384][2048] h
                 const float* __restrict__ kp, const float* __restrict__ vp,
                 const float* __restrict__ bq, const float* __restrict__ bk,
                 const float* __restrict__ bkr,
                 const float* __restrict__ bv, const float* __restrict__ bvr,
                 __half* __restrict__ outh)          // [16384][1024] h
{
    extern __shared__ __align__(16) float sm[];
    float*  ps  = sm;
    __half* qsh = reinterpret_cast<__half*>(sm + 64*PS_LD);
    __half* ksh = qsh + 64*QK_LD;
    __half* vsh = ksh + 144*QK_LD;
    __half* ph  = vsh + 144*QK_LD;

    const int seg  = blockIdx.x;
    const int h    = blockIdx.y;
    const int tid  = threadIdx.x;
    const int warp = tid >> 5;
    const int lane = tid & 31;
    const int c0   = h * 128;
    const float scale = 0.08838834764831845f;   // 1/sqrt(128)

    // q: half in, (+bq)*scale, half out to qsh
    for (int i = tid; i < 64*16; i += 256) {
        int r = i >> 4, c8 = (i & 15) << 3;
        float4 raw = *reinterpret_cast<const float4*>(qkv + (size_t)(seg*64 + r)*3072 + c0 + c8);
        const __half2* hp = reinterpret_cast<const __half2*>(&raw);
        float bv8[8];
        *reinterpret_cast<float4*>(bv8)     = *reinterpret_cast<const float4*>(bq + c0 + c8);
        *reinterpret_cast<float4*>(bv8 + 4) = *reinterpret_cast<const float4*>(bq + c0 + c8 + 4);
        __half2 o[4];
        #pragma unroll
        for (int t = 0; t < 4; t++) {
            float2 f = __half22float2(hp[t]);
            o[t] = __floats2half2_rn((f.x + bv8[2*t])*scale, (f.y + bv8[2*t+1])*scale);
        }
        *reinterpret_cast<float4*>(qsh + r*QK_LD + c8) = *reinterpret_cast<float4*>(o);
    }
    // k rows (144; >=132 zero)
    for (int i = tid; i < 144*16; i += 256) {
        int r = i >> 4, c8 = (i & 15) << 3;
        float vals[8] = {0,0,0,0,0,0,0,0};
        if (r < 64) {
            float4 raw = *reinterpret_cast<const float4*>(kvr + (size_t)(seg*64 + r)*2048 + c0 + c8);
            const __half2* hp = reinterpret_cast<const __half2*>(&raw);
            float b8[8];
            *reinterpret_cast<float4*>(b8)     = *reinterpret_cast<const float4*>(bkr + c0 + c8);
            *reinterpret_cast<float4*>(b8 + 4) = *reinterpret_cast<const float4*>(bkr + c0 + c8 + 4);
            #pragma unroll
            for (int t = 0; t < 4; t++) {
                float2 f = __half22float2(hp[t]);
                vals[2*t] = f.x + b8[2*t]; vals[2*t+1] = f.y + b8[2*t+1];
            }
        } else if (r < 68) {
            *reinterpret_cast<float4*>(vals)     = *reinterpret_cast<const float4*>(kp + (size_t)(r-64)*1024 + c0 + c8);
            *reinterpret_cast<float4*>(vals + 4) = *reinterpret_cast<const float4*>(kp + (size_t)(r-64)*1024 + c0 + c8 + 4);
        } else if (r < 132) {
            float4 raw = *reinterpret_cast<const float4*>(qkv + (size_t)(seg*64 + r - 68)*3072 + 1024 + c0 + c8);
            const __half2* hp = reinterpret_cast<const __half2*>(&raw);
            float b8[8];
            *reinterpret_cast<float4*>(b8)     = *reinterpret_cast<const float4*>(bk + c0 + c8);
            *reinterpret_cast<float4*>(b8 + 4) = *reinterpret_cast<const float4*>(bk + c0 + c8 + 4);
            #pragma unroll
            for (int t = 0; t < 4; t++) {
                float2 f = __half22float2(hp[t]);
                vals[2*t] = f.x + b8[2*t]; vals[2*t+1] = f.y + b8[2*t+1];
            }
        }
        __half2 o[4];
        #pragma unroll
        for (int t = 0; t < 4; t++) o[t] = __floats2half2_rn(vals[2*t], vals[2*t+1]);
        *reinterpret_cast<float4*>(ksh + r*QK_LD + c8) = *reinterpret_cast<float4*>(o);
    }
    // v rows (144; >=132 zero)
    for (int i = tid; i < 144*16; i += 256) {
        int r = i >> 4, c8 = (i & 15) << 3;
        float vals[8] = {0,0,0,0,0,0,0,0};
        if (r < 64) {
            float4 raw = *reinterpret_cast<const float4*>(kvr + (size_t)(seg*64 + r)*2048 + 1024 + c0 + c8);
            const __half2* hp = reinterpret_cast<const __half2*>(&raw);
            float b8[8];
            *reinterpret_cast<float4*>(b8)     = *reinterpret_cast<const float4*>(bvr + c0 + c8);
            *reinterpret_cast<float4*>(b8 + 4) = *reinterpret_cast<const float4*>(bvr + c0 + c8 + 4);
            #pragma unroll
            for (int t = 0; t < 4; t++) {
                float2 f = __half22float2(hp[t]);
                vals[2*t] = f.x + b8[2*t]; vals[2*t+1] = f.y + b8[2*t+1];
            }
        } else if (r < 68) {
            *reinterpret_cast<float4*>(vals)     = *reinterpret_cast<const float4*>(vp + (size_t)(r-64)*1024 + c0 + c8);
            *reinterpret_cast<float4*>(vals + 4) = *reinterpret_cast<const float4*>(vp + (size_t)(r-64)*1024 + c0 + c8 + 4);
        } else if (r < 132) {
            float4 raw = *reinterpret_cast<const float4*>(qkv + (size_t)(seg*64 + r - 68)*3072 + 2048 + c0 + c8);
            const __half2* hp = reinterpret_cast<const __half2*>(&raw);
            float b8[8];
            *reinterpret_cast<float4*>(b8)     = *reinterpret_cast<const float4*>(bv + c0 + c8);
            *reinterpret_cast<float4*>(b8 + 4) = *reinterpret_cast<const float4*>(bv + c0 + c8 + 4);
            #pragma unroll
            for (int t = 0; t < 4; t++) {
                float2 f = __half22float2(hp[t]);
                vals[2*t] = f.x + b8[2*t]; vals[2*t+1] = f.y + b8[2*t+1];
            }
        }
        __half2 o[4];
        #pragma unroll
        for (int t = 0; t < 4; t++) o[t] = __floats2half2_rn(vals[2*t], vals[2*t+1]);
        *reinterpret_cast<float4*>(vsh + r*QK_LD + c8) = *reinterpret_cast<float4*>(o);
    }
    __syncthreads();

    // scores = q @ k^T : 64 x 144
    for (int t = warp; t < 36; t += 8) {
        int ms = (t / 9) * 16;
        int ns = (t % 9) * 16;
        wmma::fragment<wmma::accumulator,16,16,16,float> acc;
        wmma::fill_fragment(acc, 0.0f);
        #pragma unroll
        for (int kk = 0; kk < 128; kk += 16) {
            wmma::fragment<wmma::matrix_a,16,16,16,__half,wmma::row_major> af;
            wmma::fragment<wmma::matrix_b,16,16,16,__half,wmma::col_major> bf;
            wmma::load_matrix_sync(af, qsh + ms*QK_LD + kk, QK_LD);
            wmma::load_matrix_sync(bf, ksh + ns*QK_LD + kk, QK_LD);
            wmma::mma_sync(acc, af, bf, acc);
        }
        wmma::store_matrix_sync(ps + ms*PS_LD + ns, acc, PS_LD, wmma::mem_row_major);
    }
    __syncthreads();

    // softmax (132 valid cols), normalized half probs -> ph (padded to 144)
    for (int r = warp*8; r < warp*8 + 8; r++) {
        float* row = ps + r*PS_LD;
        float m = -1e30f;
        for (int c = lane; c < 132; c += 32) m = fmaxf(m, row[c]);
        #pragma unroll
        for (int o = 16; o; o >>= 1) m = fmaxf(m, __shfl_xor_sync(0xffffffffu, m, o));
        float s = 0.f;
        for (int c = lane; c < 132; c += 32) { float e = __expf(row[c] - m); row[c] = e; s += e; }
        #pragma unroll
        for (int o = 16; o; o >>= 1) s += __shfl_xor_sync(0xffffffffu, s, o);
        float inv = 1.0f / s;
        for (int c = lane; c < 132; c += 32) ph[r*PH_LD + c] = __float2half(row[c]*inv);
        if (lane < 20) ph[r*PH_LD + 132 + lane] = __float2half(0.0f);
    }
    __syncthreads();

    // out = p @ v : accumulate f32, stage in ps, convert to half
    for (int t = warp; t < 32; t += 8) {
        int ms = (t >> 3) * 16;
        int ds = (t & 7) * 16;
        wmma::fragment<wmma::accumulator,16,16,16,float> acc;
        wmma::fill_fragment(acc, 0.0f);
        #pragma unroll
        for (int kk = 0; kk < 144; kk += 16) {
            wmma::fragment<wmma::matrix_a,16,16,16,__half,wmma::row_major> af;
            wmma::fragment<wmma::matrix_b,16,16,16,__half,wmma::row_major> bf;
            wmma::load_matrix_sync(af, ph + ms*PH_LD + kk, PH_LD);
            wmma::load_matrix_sync(bf, vsh + kk*QK_LD + ds, QK_LD);
            wmma::mma_sync(acc, af, bf, acc);
        }
        wmma::store_matrix_sync(ps + ms*PS_LD + ds, acc, PS_LD, wmma::mem_row_major);
    }
    __syncthreads();

    for (int i = tid; i < 64*16; i += 256) {
        int r = i >> 4, c8 = (i & 15) << 3;
        const float* src = ps + r*PS_LD + c8;
        __half2 o[4];
        #pragma unroll
        for (int t = 0; t < 4; t++) o[t] = __floats2half2_rn(src[2*t], src[2*t+1]);
        *reinterpret_cast<float4*>(outh + (size_t)(seg*64 + r)*1024 + c0 + c8) =
            *reinterpret_cast<float4*>(o);
    }
}

// gate blend: u = sigmoid(gpre + gate_b) * attn_biased + x  (half out)
__global__ __launch_bounds__(256)
void e2_kernel(const float* __restrict__ gpre, const float* __restrict__ gb,
               const float* __restrict__ attnb, const float* __restrict__ x,
               __half* __restrict__ u)
{
    for (size_t idx = (size_t)blockIdx.x*blockDim.x + threadIdx.x;
         idx < 16777216ull; idx += (size_t)gridDim.x*blockDim.x) {
        int c = (int)(idx & 1023);
        float g = 1.0f / (1.0f + __expf(-(gpre[idx] + gb[c])));
        u[idx] = __float2half(g * attnb[idx] + x[idx]);
    }
}

// ===========================================================================
extern "C" void kernel_launch(void* const* d_in, const int* in_sizes, int n_in,
                              void* d_out, int out_size)
{
    const float* x      = (const float*)d_in[0];
    const float* pm     = (const float*)d_in[1];
    const float* Wq     = (const float*)d_in[2];
    const float* Wk     = (const float*)d_in[3];
    const float* Wv     = (const float*)d_in[4];
    const float* mem_W1 = (const float*)d_in[5];
    const float* mem_b1 = (const float*)d_in[6];
    const float* ln1_g  = (const float*)d_in[7];
    const float* ln1_b  = (const float*)d_in[8];
    const float* mem_W2 = (const float*)d_in[9];
    const float* mem_b2 = (const float*)d_in[10];
    const float* ln2_g  = (const float*)d_in[11];
    const float* ln2_b  = (const float*)d_in[12];
    const float* mem_oW = (const float*)d_in[13];
    const float* mem_ob = (const float*)d_in[14];
    const float* mstate = (const float*)d_in[15];
    const float* mha_Wq = (const float*)d_in[16];
    const float* mha_bq = (const float*)d_in[17];
    const float* mha_Wk = (const float*)d_in[18];
    const float* mha_bk = (const float*)d_in[19];
    const float* mha_Wv = (const float*)d_in[20];
    const float* mha_bv = (const float*)d_in[21];
    const float* mha_Wo = (const float*)d_in[22];
    const float* mha_bo = (const float*)d_in[23];
    const float* gn_g   = (const float*)d_in[24];
    const float* gn_b   = (const float*)d_in[25];
    const float* gate_W = (const float*)d_in[26];
    const float* gate_b = (const float*)d_in[27];
    const float* out_W  = (const float*)d_in[28];
    const float* out_b  = (const float*)d_in[29];
    float* out = (float*)d_out;

    void* sp; cudaGetSymbolAddress(&sp, d_scratch);
    float* S0 = (float*)sp;
    float* m1    = S0;                                  // [16384][128] f32
    float* A4    = m1    + 2097152ull;                  // Wo out f32
    float* gpre  = A4    + 16777216ull;                 // gate pre f32
    float* WallS = gpre  + 16777216ull;                 // [3072][1024] f32
    float* WkrvS = WallS + 3145728ull;                  // [2048][128]
    float* W1qS  = WkrvS + 262144ull;                   // [128][1024]
    __half* xh    = (__half*)(W1qS + 131072ull);
    __half* qkvh  = xh    + 16777216ull;                // [16384][3072]
    __half* kvrh  = qkvh  + 50331648ull;                // [16384][2048]
    __half* A3h   = kvrh  + 33554432ull;
    __half* A5h   = A3h   + 16777216ull;
    __half* uh    = A5h   + 16777216ull;
    __half* m2ah  = uh    + 16777216ull;
    __half* m2h   = m2ah  + 2097152ull;
    __half* Wallh = m2h   + 2097152ull;                 // Wall|Wkrv|W1q halves
    __half* Wkrvh = Wallh + 3145728ull;
    __half* W1qh  = Wkrvh + 262144ull;
    __half* W2h   = W1qh  + 131072ull;
    __half* Woh   = W2h   + 16384ull;
    __half* gateh = Woh   + 1048576ull;
    __half* outh  = gateh + 1048576ull;
    float* kp  = (float*)(outh + 1048576ull);
    float* vp  = kp + 4096;
    float* bkr = vp + 4096;
    float* bvr = bkr + 1024;
    float* WkK = WallS + 1048576ull;
    float* WvV = WallS + 2097152ull;

    cudaFuncSetAttribute(gemm_h_kernel,        cudaFuncAttributeMaxDynamicSharedMemorySize, GSM);
    cudaFuncSetAttribute(gemm_h2_kernel<true>, cudaFuncAttributeMaxDynamicSharedMemorySize, GSM2);
    cudaFuncSetAttribute(gemm_h2_kernel<false>,cudaFuncAttributeMaxDynamicSharedMemorySize, GSM2);
    cudaFuncSetAttribute(wall_prep_kernel,     cudaFuncAttributeMaxDynamicSharedMemorySize, GSM);
    cudaFuncSetAttribute(wkrv_prep_kernel,     cudaFuncAttributeMaxDynamicSharedMemorySize, GSM);
    cudaFuncSetAttribute(attn_kernel,          cudaFuncAttributeMaxDynamicSharedMemorySize, ATTN_SMEM);

    dim3 blk(256);

    // ---- converts
    f2h_kernel<<<4096, 256>>>(x, xh, 16777216ull);
    f2h_kernel<<<512,  256>>>(mem_W2, W2h, 16384ull);
    f2h_kernel<<<2048, 256>>>(mha_Wo, Woh, 1048576ull);
    f2h_kernel<<<2048, 256>>>(gate_W, gateh, 1048576ull);
    f2h_kernel<<<2048, 256>>>(out_W, outh, 1048576ull);

    // ---- weight prep (tf32) + half conversion
    wall_prep_kernel<<<dim3(8,25), blk, GSM>>>(mha_Wq, mha_Wk, mha_Wv, mem_W1,
                                               Wq, Wk, Wv, WallS, W1qS);
    wkrv_prep_kernel<<<dim3(1,16), blk, GSM>>>(WallS, mem_oW, WkrvS);
    f2h_kernel<<<4096, 256>>>(WallS, Wallh, 3538944ull);
    fuse_bias_kernel<<<2048, 256>>>(WkK, WvV, mem_ob, mha_bk, mha_bv, bkr, bvr);
    pm_proj_kernel<<<8192, 256>>>(pm, WkK, WvV, mha_bk, mha_bv, kp, vp);

    // ---- memory net
    gemm_h_kernel<<<dim3(1,128), blk, GSM>>>(xh, W1qh, m1, 16384, 128, 1024);
    ln_mem_kernel<<<16384, 128>>>(m1, mem_b1, ln1_g, ln1_b, nullptr, m2ah, 1);
    gemm_h_kernel<<<dim3(1,128), blk, GSM>>>(m2ah, W2h, m1, 16384, 128, 128);
    ln_mem_kernel<<<16384, 128>>>(m1, mem_b2, ln2_g, ln2_b, mstate, m2h, 0);

    // ---- fused q|k|v + retrieved k|v (half outputs)
    gemm_h2_kernel<true><<<dim3(24,64), blk, GSM2>>>(xh,  Wallh, qkvh, nullptr, 16384, 3072, 1024);
    gemm_h2_kernel<true><<<dim3(16,64), blk, GSM2>>>(m2h, Wkrvh, kvrh, nullptr, 16384, 2048, 128);

    // ---- attention (half out)
    attn_kernel<<<dim3(256, 8), 256, ATTN_SMEM>>>(qkvh, kvrh, kp, vp,
                                                  mha_bq, mha_bk, bkr, mha_bv, bvr, A3h);

    // ---- output path
    gemm_h2_kernel<false><<<dim3(8,64), blk, GSM2>>>(A3h, Woh, A4, nullptr, 16384, 1024, 1024);
    biasln_c_kernel<<<16384, 256>>>(A4, mha_bo, gn_g, gn_b, A5h);
    gemm_h2_kernel<false><<<dim3(8,64), blk, GSM2>>>(A5h, gateh, gpre, nullptr, 16384, 1024, 1024);
    e2_kernel<<<8192, 256>>>(gpre, gate_b, A4, x, uh);
    gemm_h2_kernel<false><<<dim3(8,64), blk, GSM2>>>(uh, outh, out, out_b, 16384, 1024, 1024);
}